// round 1
// baseline (speedup 1.0000x reference)
#include <cuda_runtime.h>
#include <math.h>

// ---------------- constants ----------------
#define BATCH 4
#define SEQ   2048
#define EMB   2048
#define NHEAD 16
#define HDIM  128
#define MROWS (BATCH*SEQ)          // 8192
#define ELEMS ((size_t)BATCH*SEQ*EMB)   // 16777216

// ---------------- scratch (device globals: allocation-free) ----------------
__device__ float g_q[ELEMS];
__device__ float g_k[ELEMS];
__device__ float g_v[ELEMS];
__device__ float g_y[ELEMS];

// =====================================================================
// SGEMM: C[M,N] = A[M,K] * B[K,N], fp32, 128x128x16 tiles, 256 threads
// =====================================================================
#define GBM 128
#define GBN 128
#define GBK 16
#define GPAD 4

__global__ __launch_bounds__(256) void sgemm_kernel(
    const float* __restrict__ A, const float* __restrict__ B,
    float* __restrict__ C, int M, int N, int K)
{
    __shared__ float As[GBK][GBM + GPAD];  // transposed: As[k][m]
    __shared__ float Bs[GBK][GBN + GPAD];

    const int t  = threadIdx.x;
    const int tx = t & 15;
    const int ty = t >> 4;
    const int row0 = blockIdx.y * GBM;
    const int col0 = blockIdx.x * GBN;

    float acc[8][8];
#pragma unroll
    for (int i = 0; i < 8; i++)
#pragma unroll
        for (int j = 0; j < 8; j++) acc[i][j] = 0.f;

    for (int k0 = 0; k0 < K; k0 += GBK) {
        // load A tile: 128 rows x 16 cols = 512 float4
#pragma unroll
        for (int i = 0; i < 2; i++) {
            int idx = t + i * 256;
            int r   = idx >> 2;
            int c4  = (idx & 3) << 2;
            float4 av = *(const float4*)(A + (size_t)(row0 + r) * K + k0 + c4);
            As[c4 + 0][r] = av.x;
            As[c4 + 1][r] = av.y;
            As[c4 + 2][r] = av.z;
            As[c4 + 3][r] = av.w;
        }
        // load B tile: 16 rows x 128 cols = 512 float4
#pragma unroll
        for (int i = 0; i < 2; i++) {
            int idx = t + i * 256;
            int r   = idx >> 5;
            int c4  = (idx & 31) << 2;
            *(float4*)(&Bs[r][c4]) =
                *(const float4*)(B + (size_t)(k0 + r) * N + col0 + c4);
        }
        __syncthreads();

#pragma unroll
        for (int kk = 0; kk < GBK; kk++) {
            float a[8], b[8];
            *(float4*)(a)     = *(const float4*)(&As[kk][ty * 8]);
            *(float4*)(a + 4) = *(const float4*)(&As[kk][ty * 8 + 4]);
            *(float4*)(b)     = *(const float4*)(&Bs[kk][tx * 8]);
            *(float4*)(b + 4) = *(const float4*)(&Bs[kk][tx * 8 + 4]);
#pragma unroll
            for (int i = 0; i < 8; i++)
#pragma unroll
                for (int j = 0; j < 8; j++)
                    acc[i][j] = fmaf(a[i], b[j], acc[i][j]);
        }
        __syncthreads();
    }

#pragma unroll
    for (int i = 0; i < 8; i++) {
        float* cp = C + (size_t)(row0 + ty * 8 + i) * N + col0 + tx * 8;
        float4 w0 = make_float4(acc[i][0], acc[i][1], acc[i][2], acc[i][3]);
        float4 w1 = make_float4(acc[i][4], acc[i][5], acc[i][6], acc[i][7]);
        *(float4*)(cp)     = w0;
        *(float4*)(cp + 4) = w1;
    }
}

// =====================================================================
// RoPE + RMSNorm, in-place on a [B,T,H,D] buffer.
// grid = (H, T, B), block = 64 (thread i handles pair (i, i+64))
// =====================================================================
__global__ void rope_rms_kernel(float* __restrict__ buf)
{
    const int h = blockIdx.x, tp = blockIdx.y, b = blockIdx.z;
    const int i = threadIdx.x;  // 0..63
    const size_t base = ((size_t)b * SEQ + tp) * EMB + (size_t)h * HDIM;

    float x1 = buf[base + i];
    float x2 = buf[base + 64 + i];

    // angle computed in double for accuracy at large t
    double inv = exp(-((double)i / 64.0) * log(10000.0));
    double ang = (double)tp * inv;
    double sd, cd;
    sincos(ang, &sd, &cd);
    float c = (float)cd, s = (float)sd;

    float n1 = x1 * c - x2 * s;
    float n2 = x1 * s + x2 * c;

    float sq = n1 * n1 + n2 * n2;
#pragma unroll
    for (int o = 16; o > 0; o >>= 1)
        sq += __shfl_xor_sync(0xffffffffu, sq, o);

    __shared__ float partial[2];
    if ((i & 31) == 0) partial[i >> 5] = sq;
    __syncthreads();
    float tot = partial[0] + partial[1];
    float r = rsqrtf(tot * (1.0f / 128.0f) + 1.1920929e-07f);

    buf[base + i]      = n1 * r;
    buf[base + 64 + i] = n2 * r;
}

// =====================================================================
// Flash-style causal attention.
// Q,K,V,Y layout: [B, T, H, D] contiguous.
// BQ=128 queries per block, BK=64 keys per tile, 512 threads.
// Smem: Qt[d][q] (k-major transposed), Kt[d][k], Vs[k][d], Ps[q][k]
// =====================================================================
#define FBQ 128
#define FBK 64
#define QSTR 132   // FBQ + 4
#define KSTR 68    // FBK + 4
#define VSTR 132   // HDIM + 4
#define PSTR 68    // FBK + 4
#define NEG_INF (-1e30f)

#define SM_QT 0
#define SM_KT (SM_QT + HDIM*QSTR)          // 16896
#define SM_VS (SM_KT + HDIM*KSTR)          // 25600
#define SM_PS (SM_VS + FBK*VSTR)           // 34048
#define SM_M  (SM_PS + FBQ*PSTR)           // 42752
#define SM_L  (SM_M + FBQ)
#define SM_AL (SM_L + FBQ)
#define SM_TOTAL (SM_AL + FBQ)             // 43136 floats = 172544 B

__global__ __launch_bounds__(512) void flash_kernel(
    const float* __restrict__ Q, const float* __restrict__ K,
    const float* __restrict__ V, float* __restrict__ Y)
{
    extern __shared__ float sm[];
    float* Qt  = sm + SM_QT;
    float* Kt  = sm + SM_KT;
    float* Vs  = sm + SM_VS;
    float* Ps  = sm + SM_PS;
    float* m_s = sm + SM_M;
    float* l_s = sm + SM_L;
    float* a_s = sm + SM_AL;

    const int qi = gridDim.x - 1 - blockIdx.x;   // heavy blocks first
    const int h  = blockIdx.y, b = blockIdx.z;
    const int qs = qi * FBQ;
    const int t  = threadIdx.x;
    const int tx = t & 15;
    const int ty = t >> 4;     // 0..31
    const float scale = 0.08838834764831845f;  // 1/sqrt(128)

    const size_t headbase = (size_t)b * SEQ * EMB + (size_t)h * HDIM;

    // --- load Q tile (scaled), transposed to Qt[d][q] ---
#pragma unroll
    for (int i = 0; i < 8; i++) {
        int idx = t + i * 512;
        int r   = idx >> 5;
        int c4  = (idx & 31) << 2;
        float4 qv = *(const float4*)(Q + headbase + (size_t)(qs + r) * EMB + c4);
        Qt[(c4 + 0) * QSTR + r] = qv.x * scale;
        Qt[(c4 + 1) * QSTR + r] = qv.y * scale;
        Qt[(c4 + 2) * QSTR + r] = qv.z * scale;
        Qt[(c4 + 3) * QSTR + r] = qv.w * scale;
    }
    if (t < FBQ) { m_s[t] = NEG_INF; l_s[t] = 0.f; }

    float o[4][8];
#pragma unroll
    for (int i = 0; i < 4; i++)
#pragma unroll
        for (int j = 0; j < 8; j++) o[i][j] = 0.f;

    const int nkt = (qs + FBQ) / FBK;   // 2*qi + 2
    for (int jt = 0; jt < nkt; jt++) {
        const int ks = jt * FBK;
        __syncthreads();   // protect Kt/Vs/Ps from previous iteration readers

        // load K tile transposed: Kt[d][k]
#pragma unroll
        for (int i = 0; i < 4; i++) {
            int idx = t + i * 512;
            int r   = idx >> 5;
            int c4  = (idx & 31) << 2;
            float4 kv = *(const float4*)(K + headbase + (size_t)(ks + r) * EMB + c4);
            Kt[(c4 + 0) * KSTR + r] = kv.x;
            Kt[(c4 + 1) * KSTR + r] = kv.y;
            Kt[(c4 + 2) * KSTR + r] = kv.z;
            Kt[(c4 + 3) * KSTR + r] = kv.w;
        }
        // load V tile row-major: Vs[k][d]
#pragma unroll
        for (int i = 0; i < 4; i++) {
            int idx = t + i * 512;
            int r   = idx >> 5;
            int c4  = (idx & 31) << 2;
            *(float4*)(Vs + r * VSTR + c4) =
                *(const float4*)(V + headbase + (size_t)(ks + r) * EMB + c4);
        }
        __syncthreads();

        // --- S = Q K^T : rows ty*4+i, cols tx*4+j ---
        float s[4][4];
#pragma unroll
        for (int i = 0; i < 4; i++)
#pragma unroll
            for (int j = 0; j < 4; j++) s[i][j] = 0.f;

#pragma unroll 16
        for (int kk = 0; kk < HDIM; kk++) {
            float4 av = *(const float4*)(Qt + kk * QSTR + ty * 4);
            float4 bv = *(const float4*)(Kt + kk * KSTR + tx * 4);
            float a[4] = {av.x, av.y, av.z, av.w};
            float bb[4] = {bv.x, bv.y, bv.z, bv.w};
#pragma unroll
            for (int i = 0; i < 4; i++)
#pragma unroll
                for (int j = 0; j < 4; j++)
                    s[i][j] = fmaf(a[i], bb[j], s[i][j]);
        }

        // causal mask (only diagonal-region tiles)
        if (ks + FBK - 1 > qs) {
#pragma unroll
            for (int i = 0; i < 4; i++)
#pragma unroll
                for (int j = 0; j < 4; j++)
                    if (ks + tx * 4 + j > qs + ty * 4 + i) s[i][j] = NEG_INF;
        }
        // store S to Ps
#pragma unroll
        for (int i = 0; i < 4; i++) {
            float4 w = make_float4(s[i][0], s[i][1], s[i][2], s[i][3]);
            *(float4*)(Ps + (ty * 4 + i) * PSTR + tx * 4) = w;
        }
        __syncthreads();

        // --- online softmax: 4 threads per row ---
        {
            const int r  = t >> 2;
            const int qq = t & 3;
            float* prow = Ps + r * PSTR + qq * 16;
            float mloc = NEG_INF;
#pragma unroll
            for (int c = 0; c < 16; c++) mloc = fmaxf(mloc, prow[c]);
            mloc = fmaxf(mloc, __shfl_xor_sync(0xffffffffu, mloc, 1));
            mloc = fmaxf(mloc, __shfl_xor_sync(0xffffffffu, mloc, 2));
            float mold = m_s[r];
            float mnew = fmaxf(mold, mloc);
            float al   = expf(mold - mnew);
            float lsum = 0.f;
#pragma unroll
            for (int c = 0; c < 16; c++) {
                float p = expf(prow[c] - mnew);
                prow[c] = p;
                lsum += p;
            }
            lsum += __shfl_xor_sync(0xffffffffu, lsum, 1);
            lsum += __shfl_xor_sync(0xffffffffu, lsum, 2);
            if (qq == 0) {
                m_s[r] = mnew;
                a_s[r] = al;
                l_s[r] = l_s[r] * al + lsum;
            }
        }
        __syncthreads();

        // --- O = O*alpha + P @ V ---
        float alv[4];
#pragma unroll
        for (int i = 0; i < 4; i++) alv[i] = a_s[ty * 4 + i];
#pragma unroll
        for (int i = 0; i < 4; i++)
#pragma unroll
            for (int j = 0; j < 8; j++) o[i][j] *= alv[i];

#pragma unroll 8
        for (int kk = 0; kk < FBK; kk++) {
            float p[4];
#pragma unroll
            for (int i = 0; i < 4; i++) p[i] = Ps[(ty * 4 + i) * PSTR + kk];
            float4 v0 = *(const float4*)(Vs + kk * VSTR + tx * 8);
            float4 v1 = *(const float4*)(Vs + kk * VSTR + tx * 8 + 4);
            float vv[8] = {v0.x, v0.y, v0.z, v0.w, v1.x, v1.y, v1.z, v1.w};
#pragma unroll
            for (int i = 0; i < 4; i++)
#pragma unroll
                for (int j = 0; j < 8; j++)
                    o[i][j] = fmaf(p[i], vv[j], o[i][j]);
        }
    }

    // --- finalize: divide by l, write Y ---
#pragma unroll
    for (int i = 0; i < 4; i++) {
        float li = 1.0f / l_s[ty * 4 + i];
        float* yp = Y + headbase + (size_t)(qs + ty * 4 + i) * EMB + tx * 8;
        float4 w0 = make_float4(o[i][0] * li, o[i][1] * li, o[i][2] * li, o[i][3] * li);
        float4 w1 = make_float4(o[i][4] * li, o[i][5] * li, o[i][6] * li, o[i][7] * li);
        *(float4*)(yp)     = w0;
        *(float4*)(yp + 4) = w1;
    }
}

// =====================================================================
// launch
// =====================================================================
extern "C" void kernel_launch(void* const* d_in, const int* in_sizes, int n_in,
                              void* d_out, int out_size)
{
    const float* x  = (const float*)d_in[0];
    const float* wq = (const float*)d_in[1];
    const float* wk = (const float*)d_in[2];
    const float* wv = (const float*)d_in[3];
    const float* wo = (const float*)d_in[4];
    float* out = (float*)d_out;

    float *gq, *gk, *gv, *gy;
    cudaGetSymbolAddress((void**)&gq, g_q);
    cudaGetSymbolAddress((void**)&gk, g_k);
    cudaGetSymbolAddress((void**)&gv, g_v);
    cudaGetSymbolAddress((void**)&gy, g_y);

    dim3 ggrid(EMB / GBN, MROWS / GBM);   // (16, 64)
    sgemm_kernel<<<ggrid, 256>>>(x, wq, gq, MROWS, EMB, EMB);
    sgemm_kernel<<<ggrid, 256>>>(x, wk, gk, MROWS, EMB, EMB);
    sgemm_kernel<<<ggrid, 256>>>(x, wv, gv, MROWS, EMB, EMB);

    dim3 rgrid(NHEAD, SEQ, BATCH);
    rope_rms_kernel<<<rgrid, 64>>>(gq);
    rope_rms_kernel<<<rgrid, 64>>>(gk);

    const int flash_smem = SM_TOTAL * (int)sizeof(float);  // 172544 B
    cudaFuncSetAttribute(flash_kernel,
                         cudaFuncAttributeMaxDynamicSharedMemorySize, flash_smem);
    dim3 fgrid(SEQ / FBQ, NHEAD, BATCH);  // (16, 16, 4)
    flash_kernel<<<fgrid, 512, flash_smem>>>(gq, gk, gv, gy);

    sgemm_kernel<<<ggrid, 256>>>(gy, wo, out, MROWS, EMB, EMB);
}

// round 3
// speedup vs baseline: 1.5721x; 1.5721x over previous
#include <cuda_runtime.h>
#include <cuda_bf16.h>
#include <math.h>
#include <stdint.h>

// ---------------- constants ----------------
#define BATCH 4
#define SEQ   2048
#define EMB   2048
#define NHEAD 16
#define HDIM  128
#define MROWS (BATCH*SEQ)               // 8192
#define ELEMS ((size_t)BATCH*SEQ*EMB)   // 16777216

// ---------------- scratch (device globals: allocation-free) ----------------
__device__ float g_q[ELEMS];
__device__ float g_k[ELEMS];
__device__ float g_v[ELEMS];
__device__ float g_y[ELEMS];
__device__ __nv_bfloat16 g_ahi[ELEMS];          // split of x, later of y
__device__ __nv_bfloat16 g_alo[ELEMS];
__device__ __nv_bfloat16 g_wthi[(size_t)EMB*EMB];  // transposed+split weight (reused)
__device__ __nv_bfloat16 g_wtlo[(size_t)EMB*EMB];

// =====================================================================
// PTX helpers (standard sm_80+ instructions; valid on plain sm_103)
// =====================================================================
__device__ __forceinline__ uint32_t smem_to_u32(const void* p) {
    uint32_t a;
    asm("{ .reg .u64 t; cvta.to.shared.u64 t, %1; cvt.u32.u64 %0, t; }"
        : "=r"(a) : "l"(p));
    return a;
}

__device__ __forceinline__ void ldsm4(uint32_t* r, uint32_t addr) {
    asm volatile("ldmatrix.sync.aligned.m8n8.x4.shared.b16 {%0,%1,%2,%3}, [%4];"
        : "=r"(r[0]), "=r"(r[1]), "=r"(r[2]), "=r"(r[3]) : "r"(addr));
}

__device__ __forceinline__ void mma_bf16(float* c, const uint32_t* a, const uint32_t* b) {
    asm volatile(
        "mma.sync.aligned.m16n8k16.row.col.f32.bf16.bf16.f32 "
        "{%0,%1,%2,%3}, {%4,%5,%6,%7}, {%8,%9}, {%0,%1,%2,%3};"
        : "+f"(c[0]), "+f"(c[1]), "+f"(c[2]), "+f"(c[3])
        : "r"(a[0]), "r"(a[1]), "r"(a[2]), "r"(a[3]), "r"(b[0]), "r"(b[1]));
}

#define CP_ASYNC16(dst, src) \
    asm volatile("cp.async.cg.shared.global [%0], [%1], 16;" :: "r"(dst), "l"(src) : "memory")
#define CP_COMMIT() asm volatile("cp.async.commit_group;" ::: "memory")
#define CP_WAIT1()  asm volatile("cp.async.wait_group 1;" ::: "memory")
#define CP_WAIT0()  asm volatile("cp.async.wait_group 0;" ::: "memory")

// =====================================================================
// split: fp32 -> bf16 hi + bf16 lo (residual)
// =====================================================================
__global__ __launch_bounds__(256) void split_kernel(
    const float* __restrict__ in,
    __nv_bfloat16* __restrict__ hi, __nv_bfloat16* __restrict__ lo, int n4)
{
    int i = blockIdx.x * 256 + threadIdx.x;
    if (i >= n4) return;
    float4 v = ((const float4*)in)[i];
    __nv_bfloat16 h0 = __float2bfloat16(v.x);
    __nv_bfloat16 h1 = __float2bfloat16(v.y);
    __nv_bfloat16 h2 = __float2bfloat16(v.z);
    __nv_bfloat16 h3 = __float2bfloat16(v.w);
    __nv_bfloat16 l0 = __float2bfloat16(v.x - __bfloat162float(h0));
    __nv_bfloat16 l1 = __float2bfloat16(v.y - __bfloat162float(h1));
    __nv_bfloat16 l2 = __float2bfloat16(v.z - __bfloat162float(h2));
    __nv_bfloat16 l3 = __float2bfloat16(v.w - __bfloat162float(h3));
    __nv_bfloat162* hp = (__nv_bfloat162*)(hi + 4 * (size_t)i);
    __nv_bfloat162* lp = (__nv_bfloat162*)(lo + 4 * (size_t)i);
    hp[0] = __nv_bfloat162(h0, h1); hp[1] = __nv_bfloat162(h2, h3);
    lp[0] = __nv_bfloat162(l0, l1); lp[1] = __nv_bfloat162(l2, l3);
}

// =====================================================================
// weight transpose + split: W[K][N] fp32 -> WT_hi/WT_lo[N][K] bf16
// =====================================================================
__global__ __launch_bounds__(256) void wsplit_kernel(
    const float* __restrict__ w,
    __nv_bfloat16* __restrict__ hi, __nv_bfloat16* __restrict__ lo)
{
    __shared__ float tile[32][33];
    int n0 = blockIdx.x * 32, k0 = blockIdx.y * 32;
    int tx = threadIdx.x & 31, ty = threadIdx.x >> 5;  // 32 x 8
#pragma unroll
    for (int i = 0; i < 32; i += 8)
        tile[ty + i][tx] = w[(size_t)(k0 + ty + i) * EMB + n0 + tx];
    __syncthreads();
#pragma unroll
    for (int i = 0; i < 32; i += 8) {
        float v = tile[tx][ty + i];
        __nv_bfloat16 h = __float2bfloat16(v);
        size_t o = (size_t)(n0 + ty + i) * EMB + k0 + tx;
        hi[o] = h;
        lo[o] = __float2bfloat16(v - __bfloat162float(h));
    }
}

// =====================================================================
// mma.sync GEMM:  C[M,N] = A * B^T,  A/B split into bf16 hi/lo.
// A_hi/A_lo: [M][K] bf16 row-major;  B_hi/B_lo: [N][K] bf16 row-major.
// Block tile 128x128x64, 256 threads, warp tile 64x32, 2-stage cp.async.
// 3 accumulating chains: Ahi*Bhi + Ahi*Blo + Alo*Bhi  (fp32 accum).
// =====================================================================
#define BM 128
#define BN 128
#define BK 64
#define RSTRB 144                 // padded row stride in bytes (72 bf16)
#define TILE_B (128 * RSTRB)      // 18432 bytes per tile
#define STG_B  (4 * TILE_B)       // 73728 bytes per stage (Ahi,Alo,Bhi,Blo)
#define GEMM_SMEM (2 * STG_B)     // 147456 bytes

__global__ __launch_bounds__(256) void mma_gemm_kernel(
    const __nv_bfloat16* __restrict__ Ahi, const __nv_bfloat16* __restrict__ Alo,
    const __nv_bfloat16* __restrict__ Bhi, const __nv_bfloat16* __restrict__ Blo,
    float* __restrict__ C, int M, int N, int K)
{
    extern __shared__ char smc[];
    const uint32_t sb = smem_to_u32(smc);
    const int t = threadIdx.x;
    const int lane = t & 31;
    const int wid = t >> 5;
    const int warp_m = wid >> 2;     // 0..1
    const int warp_n = wid & 3;      // 0..3
    const int row0 = blockIdx.y * BM;
    const int col0 = blockIdx.x * BN;

    float acc[4][4][4];
#pragma unroll
    for (int i = 0; i < 4; i++)
#pragma unroll
        for (int j = 0; j < 4; j++)
#pragma unroll
            for (int r = 0; r < 4; r++) acc[i][j][r] = 0.f;

    const __nv_bfloat16* gsrc[4] = {Ahi, Alo, Bhi, Blo};
    const int gro[4] = {row0, row0, col0, col0};

    // ---- stage loader: 16 cp.async per thread ----
    auto load_stage = [&](int s, int k0) {
        const uint32_t base = sb + s * STG_B;
#pragma unroll
        for (int tile = 0; tile < 4; tile++) {
            const __nv_bfloat16* src = gsrc[tile];
            const int rb = gro[tile];
            const uint32_t tb = base + tile * TILE_B;
#pragma unroll
            for (int i = 0; i < 4; i++) {
                const int idx = t + i * 256;
                const int r = idx >> 3;
                const int c = idx & 7;
                const uint32_t d = tb + r * RSTRB + c * 16;
                const __nv_bfloat16* g = src + (size_t)(rb + r) * K + k0 + c * 8;
                CP_ASYNC16(d, g);
            }
        }
    };

    const int nIter = K / BK;
    load_stage(0, 0);
    CP_COMMIT();

    for (int it = 0; it < nIter; it++) {
        if (it + 1 < nIter) {
            load_stage((it + 1) & 1, (it + 1) * BK);
            CP_COMMIT();
            CP_WAIT1();
        } else {
            CP_WAIT0();
        }
        __syncthreads();

        const uint32_t abase = sb + (it & 1) * STG_B;
        const int arow = warp_m * 64 + (lane & 15);
        const int brow = warp_n * 32 + ((lane >> 4) << 3) + (lane & 7);

#pragma unroll
        for (int ks = 0; ks < 4; ks++) {
            uint32_t ah[4][4], al[4][4], bh[2][4], bl[2][4];
            const uint32_t acol = ks * 32 + ((lane >> 4) << 4);
            const uint32_t bcol = ks * 32 + (((lane >> 3) & 1) << 4);
#pragma unroll
            for (int mf = 0; mf < 4; mf++) {
                const uint32_t ad = abase + (arow + mf * 16) * RSTRB + acol;
                ldsm4(ah[mf], ad);
                ldsm4(al[mf], ad + TILE_B);
            }
#pragma unroll
            for (int np = 0; np < 2; np++) {
                const uint32_t bd = abase + 2 * TILE_B + (brow + np * 16) * RSTRB + bcol;
                ldsm4(bh[np], bd);
                ldsm4(bl[np], bd + TILE_B);
            }
#pragma unroll
            for (int mf = 0; mf < 4; mf++) {
#pragma unroll
                for (int nf = 0; nf < 4; nf++) {
                    const uint32_t* bhp = &bh[nf >> 1][(nf & 1) * 2];
                    const uint32_t* blp = &bl[nf >> 1][(nf & 1) * 2];
                    mma_bf16(acc[mf][nf], ah[mf], bhp);
                    mma_bf16(acc[mf][nf], ah[mf], blp);
                    mma_bf16(acc[mf][nf], al[mf], bhp);
                }
            }
        }
        __syncthreads();
    }

    // ---- epilogue: direct float2 stores ----
    const int mbase = row0 + warp_m * 64 + (lane >> 2);
    const int nbase = col0 + warp_n * 32 + (lane & 3) * 2;
#pragma unroll
    for (int mf = 0; mf < 4; mf++) {
#pragma unroll
        for (int nf = 0; nf < 4; nf++) {
            const size_t o0 = (size_t)(mbase + mf * 16) * N + nbase + nf * 8;
            const size_t o1 = (size_t)(mbase + mf * 16 + 8) * N + nbase + nf * 8;
            *(float2*)(C + o0) = make_float2(acc[mf][nf][0], acc[mf][nf][1]);
            *(float2*)(C + o1) = make_float2(acc[mf][nf][2], acc[mf][nf][3]);
        }
    }
}

// =====================================================================
// RoPE + RMSNorm, in-place on a [B,T,H,D] buffer.
// =====================================================================
__global__ void rope_rms_kernel(float* __restrict__ buf)
{
    const int h = blockIdx.x, tp = blockIdx.y, b = blockIdx.z;
    const int i = threadIdx.x;  // 0..63
    const size_t base = ((size_t)b * SEQ + tp) * EMB + (size_t)h * HDIM;

    float x1 = buf[base + i];
    float x2 = buf[base + 64 + i];

    double inv = exp(-((double)i / 64.0) * log(10000.0));
    double ang = (double)tp * inv;
    double sd, cd;
    sincos(ang, &sd, &cd);
    float c = (float)cd, s = (float)sd;

    float n1 = x1 * c - x2 * s;
    float n2 = x1 * s + x2 * c;

    float sq = n1 * n1 + n2 * n2;
#pragma unroll
    for (int o = 16; o > 0; o >>= 1)
        sq += __shfl_xor_sync(0xffffffffu, sq, o);

    __shared__ float partial[2];
    if ((i & 31) == 0) partial[i >> 5] = sq;
    __syncthreads();
    float tot = partial[0] + partial[1];
    float r = rsqrtf(tot * (1.0f / 128.0f) + 1.1920929e-07f);

    buf[base + i]      = n1 * r;
    buf[base + 64 + i] = n2 * r;
}

// =====================================================================
// Flash-style causal attention (SIMT fp32) — unchanged from R1.
// =====================================================================
#define FBQ 128
#define FBK 64
#define QSTR 132
#define KSTR 68
#define VSTR 132
#define PSTR 68
#define NEG_INF (-1e30f)

#define SM_QT 0
#define SM_KT (SM_QT + HDIM*QSTR)
#define SM_VS (SM_KT + HDIM*KSTR)
#define SM_PS (SM_VS + FBK*VSTR)
#define SM_M  (SM_PS + FBQ*PSTR)
#define SM_L  (SM_M + FBQ)
#define SM_AL (SM_L + FBQ)
#define SM_TOTAL (SM_AL + FBQ)

__global__ __launch_bounds__(512) void flash_kernel(
    const float* __restrict__ Q, const float* __restrict__ K,
    const float* __restrict__ V, float* __restrict__ Y)
{
    extern __shared__ float smf[];
    float* Qt  = smf + SM_QT;
    float* Kt  = smf + SM_KT;
    float* Vs  = smf + SM_VS;
    float* Ps  = smf + SM_PS;
    float* m_s = smf + SM_M;
    float* l_s = smf + SM_L;
    float* a_s = smf + SM_AL;

    const int qi = gridDim.x - 1 - blockIdx.x;
    const int h  = blockIdx.y, b = blockIdx.z;
    const int qs = qi * FBQ;
    const int t  = threadIdx.x;
    const int tx = t & 15;
    const int ty = t >> 4;
    const float scale = 0.08838834764831845f;

    const size_t headbase = (size_t)b * SEQ * EMB + (size_t)h * HDIM;

#pragma unroll
    for (int i = 0; i < 8; i++) {
        int idx = t + i * 512;
        int r   = idx >> 5;
        int c4  = (idx & 31) << 2;
        float4 qv = *(const float4*)(Q + headbase + (size_t)(qs + r) * EMB + c4);
        Qt[(c4 + 0) * QSTR + r] = qv.x * scale;
        Qt[(c4 + 1) * QSTR + r] = qv.y * scale;
        Qt[(c4 + 2) * QSTR + r] = qv.z * scale;
        Qt[(c4 + 3) * QSTR + r] = qv.w * scale;
    }
    if (t < FBQ) { m_s[t] = NEG_INF; l_s[t] = 0.f; }

    float o[4][8];
#pragma unroll
    for (int i = 0; i < 4; i++)
#pragma unroll
        for (int jj = 0; jj < 8; jj++) o[i][jj] = 0.f;

    const int nkt = (qs + FBQ) / FBK;
    for (int jt = 0; jt < nkt; jt++) {
        const int ks = jt * FBK;
        __syncthreads();

#pragma unroll
        for (int i = 0; i < 4; i++) {
            int idx = t + i * 512;
            int r   = idx >> 5;
            int c4  = (idx & 31) << 2;
            float4 kv = *(const float4*)(K + headbase + (size_t)(ks + r) * EMB + c4);
            Kt[(c4 + 0) * KSTR + r] = kv.x;
            Kt[(c4 + 1) * KSTR + r] = kv.y;
            Kt[(c4 + 2) * KSTR + r] = kv.z;
            Kt[(c4 + 3) * KSTR + r] = kv.w;
        }
#pragma unroll
        for (int i = 0; i < 4; i++) {
            int idx = t + i * 512;
            int r   = idx >> 5;
            int c4  = (idx & 31) << 2;
            *(float4*)(Vs + r * VSTR + c4) =
                *(const float4*)(V + headbase + (size_t)(ks + r) * EMB + c4);
        }
        __syncthreads();

        float s[4][4];
#pragma unroll
        for (int i = 0; i < 4; i++)
#pragma unroll
            for (int jj = 0; jj < 4; jj++) s[i][jj] = 0.f;

#pragma unroll 16
        for (int kk = 0; kk < HDIM; kk++) {
            float4 av = *(const float4*)(Qt + kk * QSTR + ty * 4);
            float4 bv = *(const float4*)(Kt + kk * KSTR + tx * 4);
            float a[4] = {av.x, av.y, av.z, av.w};
            float bb[4] = {bv.x, bv.y, bv.z, bv.w};
#pragma unroll
            for (int i = 0; i < 4; i++)
#pragma unroll
                for (int jj = 0; jj < 4; jj++)
                    s[i][jj] = fmaf(a[i], bb[jj], s[i][jj]);
        }

        if (ks + FBK - 1 > qs) {
#pragma unroll
            for (int i = 0; i < 4; i++)
#pragma unroll
                for (int jj = 0; jj < 4; jj++)
                    if (ks + tx * 4 + jj > qs + ty * 4 + i) s[i][jj] = NEG_INF;
        }
#pragma unroll
        for (int i = 0; i < 4; i++) {
            float4 w = make_float4(s[i][0], s[i][1], s[i][2], s[i][3]);
            *(float4*)(Ps + (ty * 4 + i) * PSTR + tx * 4) = w;
        }
        __syncthreads();

        {
            const int r  = t >> 2;
            const int qq = t & 3;
            float* prow = Ps + r * PSTR + qq * 16;
            float mloc = NEG_INF;
#pragma unroll
            for (int cc = 0; cc < 16; cc++) mloc = fmaxf(mloc, prow[cc]);
            mloc = fmaxf(mloc, __shfl_xor_sync(0xffffffffu, mloc, 1));
            mloc = fmaxf(mloc, __shfl_xor_sync(0xffffffffu, mloc, 2));
            float mold = m_s[r];
            float mnew = fmaxf(mold, mloc);
            float al   = expf(mold - mnew);
            float lsum = 0.f;
#pragma unroll
            for (int cc = 0; cc < 16; cc++) {
                float p = expf(prow[cc] - mnew);
                prow[cc] = p;
                lsum += p;
            }
            lsum += __shfl_xor_sync(0xffffffffu, lsum, 1);
            lsum += __shfl_xor_sync(0xffffffffu, lsum, 2);
            if (qq == 0) {
                m_s[r] = mnew;
                a_s[r] = al;
                l_s[r] = l_s[r] * al + lsum;
            }
        }
        __syncthreads();

        float alv[4];
#pragma unroll
        for (int i = 0; i < 4; i++) alv[i] = a_s[ty * 4 + i];
#pragma unroll
        for (int i = 0; i < 4; i++)
#pragma unroll
            for (int jj = 0; jj < 8; jj++) o[i][jj] *= alv[i];

#pragma unroll 8
        for (int kk = 0; kk < FBK; kk++) {
            float p[4];
#pragma unroll
            for (int i = 0; i < 4; i++) p[i] = Ps[(ty * 4 + i) * PSTR + kk];
            float4 v0 = *(const float4*)(Vs + kk * VSTR + tx * 8);
            float4 v1 = *(const float4*)(Vs + kk * VSTR + tx * 8 + 4);
            float vv[8] = {v0.x, v0.y, v0.z, v0.w, v1.x, v1.y, v1.z, v1.w};
#pragma unroll
            for (int i = 0; i < 4; i++)
#pragma unroll
                for (int jj = 0; jj < 8; jj++)
                    o[i][jj] = fmaf(p[i], vv[jj], o[i][jj]);
        }
    }

#pragma unroll
    for (int i = 0; i < 4; i++) {
        float li = 1.0f / l_s[ty * 4 + i];
        float* yp = Y + headbase + (size_t)(qs + ty * 4 + i) * EMB + tx * 8;
        float4 w0 = make_float4(o[i][0] * li, o[i][1] * li, o[i][2] * li, o[i][3] * li);
        float4 w1 = make_float4(o[i][4] * li, o[i][5] * li, o[i][6] * li, o[i][7] * li);
        *(float4*)(yp)     = w0;
        *(float4*)(yp + 4) = w1;
    }
}

// =====================================================================
// launch
// =====================================================================
extern "C" void kernel_launch(void* const* d_in, const int* in_sizes, int n_in,
                              void* d_out, int out_size)
{
    const float* x  = (const float*)d_in[0];
    const float* wq = (const float*)d_in[1];
    const float* wk = (const float*)d_in[2];
    const float* wv = (const float*)d_in[3];
    const float* wo = (const float*)d_in[4];
    float* out = (float*)d_out;

    float *gq, *gk, *gv, *gy;
    __nv_bfloat16 *ahi, *alo, *wthi, *wtlo;
    cudaGetSymbolAddress((void**)&gq, g_q);
    cudaGetSymbolAddress((void**)&gk, g_k);
    cudaGetSymbolAddress((void**)&gv, g_v);
    cudaGetSymbolAddress((void**)&gy, g_y);
    cudaGetSymbolAddress((void**)&ahi, g_ahi);
    cudaGetSymbolAddress((void**)&alo, g_alo);
    cudaGetSymbolAddress((void**)&wthi, g_wthi);
    cudaGetSymbolAddress((void**)&wtlo, g_wtlo);

    cudaFuncSetAttribute(mma_gemm_kernel,
                         cudaFuncAttributeMaxDynamicSharedMemorySize, GEMM_SMEM);

    const int n4 = (int)(ELEMS / 4);
    const dim3 sgrid((n4 + 255) / 256);
    const dim3 wgrid(EMB / 32, EMB / 32);       // (64, 64)
    const dim3 ggrid(EMB / BN, MROWS / BM);     // (16, 64)

    // split x
    split_kernel<<<sgrid, 256>>>(x, ahi, alo, n4);

    // Q = x @ wq
    wsplit_kernel<<<wgrid, 256>>>(wq, wthi, wtlo);
    mma_gemm_kernel<<<ggrid, 256, GEMM_SMEM>>>(ahi, alo, wthi, wtlo, gq, MROWS, EMB, EMB);
    // K = x @ wk
    wsplit_kernel<<<wgrid, 256>>>(wk, wthi, wtlo);
    mma_gemm_kernel<<<ggrid, 256, GEMM_SMEM>>>(ahi, alo, wthi, wtlo, gk, MROWS, EMB, EMB);
    // V = x @ wv
    wsplit_kernel<<<wgrid, 256>>>(wv, wthi, wtlo);
    mma_gemm_kernel<<<ggrid, 256, GEMM_SMEM>>>(ahi, alo, wthi, wtlo, gv, MROWS, EMB, EMB);

    // RoPE + RMSNorm
    dim3 rgrid(NHEAD, SEQ, BATCH);
    rope_rms_kernel<<<rgrid, 64>>>(gq);
    rope_rms_kernel<<<rgrid, 64>>>(gk);

    // flash attention
    const int flash_smem = SM_TOTAL * (int)sizeof(float);
    cudaFuncSetAttribute(flash_kernel,
                         cudaFuncAttributeMaxDynamicSharedMemorySize, flash_smem);
    dim3 fgrid(SEQ / FBQ, NHEAD, BATCH);
    flash_kernel<<<fgrid, 512, flash_smem>>>(gq, gk, gv, gy);

    // out = y @ wo
    split_kernel<<<sgrid, 256>>>(gy, ahi, alo, n4);
    wsplit_kernel<<<wgrid, 256>>>(wo, wthi, wtlo);
    mma_gemm_kernel<<<ggrid, 256, GEMM_SMEM>>>(ahi, alo, wthi, wtlo, out, MROWS, EMB, EMB);
}

// round 4
// speedup vs baseline: 2.2287x; 1.4177x over previous
#include <cuda_runtime.h>
#include <cuda_bf16.h>
#include <math.h>
#include <stdint.h>

// ---------------- constants ----------------
#define BATCH 4
#define SEQ   2048
#define EMB   2048
#define NHEAD 16
#define HDIM  128
#define MROWS (BATCH*SEQ)               // 8192
#define ELEMS ((size_t)BATCH*SEQ*EMB)   // 16777216
#define L2E   1.4426950408889634f

// ---------------- scratch (device globals: allocation-free) ----------------
__device__ float g_q[ELEMS];
__device__ float g_k[ELEMS];
__device__ float g_v[ELEMS];
__device__ float g_y[ELEMS];
__device__ __nv_bfloat16 g_ahi[ELEMS];
__device__ __nv_bfloat16 g_alo[ELEMS];
__device__ __nv_bfloat16 g_wthi[(size_t)EMB*EMB];
__device__ __nv_bfloat16 g_wtlo[(size_t)EMB*EMB];
__device__ __nv_bfloat16 g_qh[ELEMS];
__device__ __nv_bfloat16 g_ql[ELEMS];
__device__ __nv_bfloat16 g_kh[ELEMS];
__device__ __nv_bfloat16 g_kl[ELEMS];
__device__ __nv_bfloat16 g_vh[ELEMS];
__device__ __nv_bfloat16 g_vl[ELEMS];

// =====================================================================
// PTX helpers (standard sm_80+ instructions; valid on plain sm_103)
// =====================================================================
__device__ __forceinline__ uint32_t smem_to_u32(const void* p) {
    uint32_t a;
    asm("{ .reg .u64 t; cvta.to.shared.u64 t, %1; cvt.u32.u64 %0, t; }"
        : "=r"(a) : "l"(p));
    return a;
}

__device__ __forceinline__ void ldsm4(uint32_t* r, uint32_t addr) {
    asm volatile("ldmatrix.sync.aligned.m8n8.x4.shared.b16 {%0,%1,%2,%3}, [%4];"
        : "=r"(r[0]), "=r"(r[1]), "=r"(r[2]), "=r"(r[3]) : "r"(addr));
}
__device__ __forceinline__ void ldsm4t(uint32_t* r, uint32_t addr) {
    asm volatile("ldmatrix.sync.aligned.m8n8.x4.trans.shared.b16 {%0,%1,%2,%3}, [%4];"
        : "=r"(r[0]), "=r"(r[1]), "=r"(r[2]), "=r"(r[3]) : "r"(addr));
}

__device__ __forceinline__ void mma_bf16(float* c, const uint32_t* a, const uint32_t* b) {
    asm volatile(
        "mma.sync.aligned.m16n8k16.row.col.f32.bf16.bf16.f32 "
        "{%0,%1,%2,%3}, {%4,%5,%6,%7}, {%8,%9}, {%0,%1,%2,%3};"
        : "+f"(c[0]), "+f"(c[1]), "+f"(c[2]), "+f"(c[3])
        : "r"(a[0]), "r"(a[1]), "r"(a[2]), "r"(a[3]), "r"(b[0]), "r"(b[1]));
}

// pack two f32 into bf16x2: lower half = lo, upper half = hi
__device__ __forceinline__ uint32_t pack_bf16x2(float lo, float hi) {
    uint32_t r;
    asm("cvt.rn.bf16x2.f32 %0, %1, %2;" : "=r"(r) : "f"(hi), "f"(lo));
    return r;
}

#define CP_ASYNC16(dst, src) \
    asm volatile("cp.async.cg.shared.global [%0], [%1], 16;" :: "r"(dst), "l"(src) : "memory")
#define CP_COMMIT() asm volatile("cp.async.commit_group;" ::: "memory")
#define CP_WAIT1()  asm volatile("cp.async.wait_group 1;" ::: "memory")
#define CP_WAIT0()  asm volatile("cp.async.wait_group 0;" ::: "memory")

// =====================================================================
// split: fp32 -> bf16 hi + bf16 lo (residual)
// =====================================================================
__global__ __launch_bounds__(256) void split_kernel(
    const float* __restrict__ in,
    __nv_bfloat16* __restrict__ hi, __nv_bfloat16* __restrict__ lo, int n4)
{
    int i = blockIdx.x * 256 + threadIdx.x;
    if (i >= n4) return;
    float4 v = ((const float4*)in)[i];
    __nv_bfloat16 h0 = __float2bfloat16(v.x);
    __nv_bfloat16 h1 = __float2bfloat16(v.y);
    __nv_bfloat16 h2 = __float2bfloat16(v.z);
    __nv_bfloat16 h3 = __float2bfloat16(v.w);
    __nv_bfloat16 l0 = __float2bfloat16(v.x - __bfloat162float(h0));
    __nv_bfloat16 l1 = __float2bfloat16(v.y - __bfloat162float(h1));
    __nv_bfloat16 l2 = __float2bfloat16(v.z - __bfloat162float(h2));
    __nv_bfloat16 l3 = __float2bfloat16(v.w - __bfloat162float(h3));
    __nv_bfloat162* hp = (__nv_bfloat162*)(hi + 4 * (size_t)i);
    __nv_bfloat162* lp = (__nv_bfloat162*)(lo + 4 * (size_t)i);
    hp[0] = __nv_bfloat162(h0, h1); hp[1] = __nv_bfloat162(h2, h3);
    lp[0] = __nv_bfloat162(l0, l1); lp[1] = __nv_bfloat162(l2, l3);
}

// =====================================================================
// weight transpose + split: W[K][N] fp32 -> WT_hi/WT_lo[N][K] bf16
// =====================================================================
__global__ __launch_bounds__(256) void wsplit_kernel(
    const float* __restrict__ w,
    __nv_bfloat16* __restrict__ hi, __nv_bfloat16* __restrict__ lo)
{
    __shared__ float tile[32][33];
    int n0 = blockIdx.x * 32, k0 = blockIdx.y * 32;
    int tx = threadIdx.x & 31, ty = threadIdx.x >> 5;
#pragma unroll
    for (int i = 0; i < 32; i += 8)
        tile[ty + i][tx] = w[(size_t)(k0 + ty + i) * EMB + n0 + tx];
    __syncthreads();
#pragma unroll
    for (int i = 0; i < 32; i += 8) {
        float v = tile[tx][ty + i];
        __nv_bfloat16 h = __float2bfloat16(v);
        size_t o = (size_t)(n0 + ty + i) * EMB + k0 + tx;
        hi[o] = h;
        lo[o] = __float2bfloat16(v - __bfloat162float(h));
    }
}

// =====================================================================
// mma.sync GEMM (unchanged from R3): C = A * B^T, split bf16 3-chain
// =====================================================================
#define BM 128
#define BN 128
#define BK 64
#define RSTRB 144
#define TILE_B (128 * RSTRB)
#define STG_B  (4 * TILE_B)
#define GEMM_SMEM (2 * STG_B)

__global__ __launch_bounds__(256) void mma_gemm_kernel(
    const __nv_bfloat16* __restrict__ Ahi, const __nv_bfloat16* __restrict__ Alo,
    const __nv_bfloat16* __restrict__ Bhi, const __nv_bfloat16* __restrict__ Blo,
    float* __restrict__ C, int M, int N, int K)
{
    extern __shared__ char smc[];
    const uint32_t sb = smem_to_u32(smc);
    const int t = threadIdx.x;
    const int lane = t & 31;
    const int wid = t >> 5;
    const int warp_m = wid >> 2;
    const int warp_n = wid & 3;
    const int row0 = blockIdx.y * BM;
    const int col0 = blockIdx.x * BN;

    float acc[4][4][4];
#pragma unroll
    for (int i = 0; i < 4; i++)
#pragma unroll
        for (int j = 0; j < 4; j++)
#pragma unroll
            for (int r = 0; r < 4; r++) acc[i][j][r] = 0.f;

    const __nv_bfloat16* gsrc[4] = {Ahi, Alo, Bhi, Blo};
    const int gro[4] = {row0, row0, col0, col0};

    auto load_stage = [&](int s, int k0) {
        const uint32_t base = sb + s * STG_B;
#pragma unroll
        for (int tile = 0; tile < 4; tile++) {
            const __nv_bfloat16* src = gsrc[tile];
            const int rb = gro[tile];
            const uint32_t tb = base + tile * TILE_B;
#pragma unroll
            for (int i = 0; i < 4; i++) {
                const int idx = t + i * 256;
                const int r = idx >> 3;
                const int c = idx & 7;
                const uint32_t d = tb + r * RSTRB + c * 16;
                const __nv_bfloat16* g = src + (size_t)(rb + r) * K + k0 + c * 8;
                CP_ASYNC16(d, g);
            }
        }
    };

    const int nIter = K / BK;
    load_stage(0, 0);
    CP_COMMIT();

    for (int it = 0; it < nIter; it++) {
        if (it + 1 < nIter) {
            load_stage((it + 1) & 1, (it + 1) * BK);
            CP_COMMIT();
            CP_WAIT1();
        } else {
            CP_WAIT0();
        }
        __syncthreads();

        const uint32_t abase = sb + (it & 1) * STG_B;
        const int arow = warp_m * 64 + (lane & 15);
        const int brow = warp_n * 32 + ((lane >> 4) << 3) + (lane & 7);

#pragma unroll
        for (int ks = 0; ks < 4; ks++) {
            uint32_t ah[4][4], al[4][4], bh[2][4], bl[2][4];
            const uint32_t acol = ks * 32 + ((lane >> 4) << 4);
            const uint32_t bcol = ks * 32 + (((lane >> 3) & 1) << 4);
#pragma unroll
            for (int mf = 0; mf < 4; mf++) {
                const uint32_t ad = abase + (arow + mf * 16) * RSTRB + acol;
                ldsm4(ah[mf], ad);
                ldsm4(al[mf], ad + TILE_B);
            }
#pragma unroll
            for (int np = 0; np < 2; np++) {
                const uint32_t bd = abase + 2 * TILE_B + (brow + np * 16) * RSTRB + bcol;
                ldsm4(bh[np], bd);
                ldsm4(bl[np], bd + TILE_B);
            }
#pragma unroll
            for (int mf = 0; mf < 4; mf++) {
#pragma unroll
                for (int nf = 0; nf < 4; nf++) {
                    const uint32_t* bhp = &bh[nf >> 1][(nf & 1) * 2];
                    const uint32_t* blp = &bl[nf >> 1][(nf & 1) * 2];
                    mma_bf16(acc[mf][nf], ah[mf], bhp);
                    mma_bf16(acc[mf][nf], ah[mf], blp);
                    mma_bf16(acc[mf][nf], al[mf], bhp);
                }
            }
        }
        __syncthreads();
    }

    const int mbase = row0 + warp_m * 64 + (lane >> 2);
    const int nbase = col0 + warp_n * 32 + (lane & 3) * 2;
#pragma unroll
    for (int mf = 0; mf < 4; mf++) {
#pragma unroll
        for (int nf = 0; nf < 4; nf++) {
            const size_t o0 = (size_t)(mbase + mf * 16) * N + nbase + nf * 8;
            const size_t o1 = (size_t)(mbase + mf * 16 + 8) * N + nbase + nf * 8;
            *(float2*)(C + o0) = make_float2(acc[mf][nf][0], acc[mf][nf][1]);
            *(float2*)(C + o1) = make_float2(acc[mf][nf][2], acc[mf][nf][3]);
        }
    }
}

// =====================================================================
// RoPE + RMSNorm + scale + bf16 hi/lo split (fused prep for flash)
// grid = (H, T, B), block = 64
// =====================================================================
__global__ void ropeprep_kernel(const float* __restrict__ buf,
                                __nv_bfloat16* __restrict__ hi,
                                __nv_bfloat16* __restrict__ lo,
                                float outscale)
{
    const int h = blockIdx.x, tp = blockIdx.y, b = blockIdx.z;
    const int i = threadIdx.x;  // 0..63
    const size_t base = ((size_t)b * SEQ + tp) * EMB + (size_t)h * HDIM;

    float x1 = buf[base + i];
    float x2 = buf[base + 64 + i];

    double inv = exp(-((double)i / 64.0) * log(10000.0));
    double ang = (double)tp * inv;
    double sd, cd;
    sincos(ang, &sd, &cd);
    float c = (float)cd, s = (float)sd;

    float n1 = x1 * c - x2 * s;
    float n2 = x1 * s + x2 * c;

    float sq = n1 * n1 + n2 * n2;
#pragma unroll
    for (int o = 16; o > 0; o >>= 1)
        sq += __shfl_xor_sync(0xffffffffu, sq, o);

    __shared__ float partial[2];
    if ((i & 31) == 0) partial[i >> 5] = sq;
    __syncthreads();
    float tot = partial[0] + partial[1];
    float r = rsqrtf(tot * (1.0f / 128.0f) + 1.1920929e-07f) * outscale;

    float y1 = n1 * r, y2 = n2 * r;
    __nv_bfloat16 h1 = __float2bfloat16(y1);
    __nv_bfloat16 h2 = __float2bfloat16(y2);
    hi[base + i]      = h1;
    hi[base + 64 + i] = h2;
    lo[base + i]      = __float2bfloat16(y1 - __bfloat162float(h1));
    lo[base + 64 + i] = __float2bfloat16(y2 - __bfloat162float(h2));
}

// =====================================================================
// Flash attention on mma.sync bf16 (split hi/lo, 3 chains both GEMMs).
// BQ=128, BK=64, 256 threads; warp w owns query rows [w*16, w*16+16).
// smem: region0 = Q (hi 128 rows + lo 128 rows), regions 1,2 = KV stages.
// =====================================================================
#define FL_STR  136                 // padded row stride (bf16 elems)
#define FL_ROWB (FL_STR*2)          // 272 bytes
#define FL_TILE (64*FL_ROWB)        // 17408 B (one 64-row tile)
#define FL_STG  (4*FL_TILE)         // 69632 B (Khi,Klo,Vhi,Vlo)
#define FL_QLO  (128*FL_ROWB)       // 34816 (Qlo offset inside region0)
#define FL_SMEM (3*FL_STG)          // 208896 B

__global__ __launch_bounds__(256, 1) void flash_mma_kernel(
    const __nv_bfloat16* __restrict__ Qh, const __nv_bfloat16* __restrict__ Ql,
    const __nv_bfloat16* __restrict__ Kh, const __nv_bfloat16* __restrict__ Kl,
    const __nv_bfloat16* __restrict__ Vh, const __nv_bfloat16* __restrict__ Vl,
    float* __restrict__ Y)
{
    extern __shared__ char smc[];
    const uint32_t sb = smem_to_u32(smc);
    const int t = threadIdx.x;
    const int lane = t & 31;
    const int w = t >> 5;
    const int qi = gridDim.x - 1 - blockIdx.x;    // heavy first
    const int h = blockIdx.y, b = blockIdx.z;
    const int qs = qi * 128;
    const size_t hb = ((size_t)b * SEQ) * EMB + (size_t)h * HDIM;

    // ---- load Q (hi + lo) into region0 via cp.async ----
#pragma unroll
    for (int i = 0; i < 8; i++) {
        const int idx = t + i * 256;          // 0..2047
        const int r = idx >> 4, c = idx & 15;
        const size_t g = hb + (size_t)(qs + r) * EMB + c * 8;
        CP_ASYNC16(sb + r * FL_ROWB + c * 16, Qh + g);
        CP_ASYNC16(sb + FL_QLO + r * FL_ROWB + c * 16, Ql + g);
    }
    CP_COMMIT();

    // ---- KV stage loader ----
    auto load_kv = [&](int s, int ks) {
        const uint32_t base = sb + FL_STG * (1 + s);
        const __nv_bfloat16* srcs[4] = {Kh, Kl, Vh, Vl};
#pragma unroll
        for (int tile = 0; tile < 4; tile++) {
#pragma unroll
            for (int i = 0; i < 4; i++) {
                const int idx = t + i * 256;  // 0..1023
                const int r = idx >> 4, c = idx & 15;
                CP_ASYNC16(base + tile * FL_TILE + r * FL_ROWB + c * 16,
                           srcs[tile] + hb + (size_t)(ks + r) * EMB + c * 8);
            }
        }
    };

    load_kv(0, 0);
    CP_COMMIT();

    // ---- per-thread softmax state (rows r0, r1 = r0+8) ----
    float m0 = -INFINITY, m1 = -INFINITY, l0 = 0.f, l1 = 0.f;
    float o[16][4];
#pragma unroll
    for (int i = 0; i < 16; i++)
#pragma unroll
        for (int j = 0; j < 4; j++) o[i][j] = 0.f;

    // ldmatrix lane-dependent address components
    const uint32_t q_addr = sb + (w * 16 + (lane & 15)) * FL_ROWB + (lane >> 4) * 16;
    const int krow = (lane & 7) + ((lane >> 4) << 3);
    const uint32_t kcolb = ((lane >> 3) & 1) * 16;
    const int vrow = (lane & 7) + (((lane >> 3) & 1) << 3);
    const uint32_t vcolb = (lane >> 4) * 16;

    const int r0g = qs + w * 16 + (lane >> 2);
    const int r1g = r0g + 8;
    const int nkt = (qs + 128) / 64;

    for (int jt = 0; jt < nkt; jt++) {
        CP_WAIT0();
        __syncthreads();
        if (jt + 1 < nkt) { load_kv((jt + 1) & 1, (jt + 1) * 64); CP_COMMIT(); }

        const int ks = jt * 64;
        if (ks <= qs + w * 16 + 15) {   // warp has at least one unmasked row
            const uint32_t kb = sb + FL_STG * (1 + (jt & 1));

            // ---- S = Q K^T (3 chains) ----
            float s[8][4];
#pragma unroll
            for (int i = 0; i < 8; i++)
#pragma unroll
                for (int j = 0; j < 4; j++) s[i][j] = 0.f;

#pragma unroll
            for (int kf = 0; kf < 8; kf++) {
                uint32_t qa[4], qla[4];
                ldsm4(qa, q_addr + kf * 32);
                ldsm4(qla, q_addr + FL_QLO + kf * 32);
#pragma unroll
                for (int nfp = 0; nfp < 4; nfp++) {
                    uint32_t kh4[4], kl4[4];
                    const uint32_t ka = kb + (nfp * 16 + krow) * FL_ROWB + kcolb + kf * 32;
                    ldsm4(kh4, ka);
                    ldsm4(kl4, ka + FL_TILE);
                    mma_bf16(s[2 * nfp], qa, kh4);
                    mma_bf16(s[2 * nfp], qa, kl4);
                    mma_bf16(s[2 * nfp], qla, kh4);
                    mma_bf16(s[2 * nfp + 1], qa, kh4 + 2);
                    mma_bf16(s[2 * nfp + 1], qa, kl4 + 2);
                    mma_bf16(s[2 * nfp + 1], qla, kh4 + 2);
                }
            }

            // ---- causal mask ----
            if (ks + 63 > r0g) {
#pragma unroll
                for (int nf = 0; nf < 8; nf++) {
                    const int kc = ks + nf * 8 + (lane & 3) * 2;
                    if (kc > r0g)     s[nf][0] = -1e30f;
                    if (kc + 1 > r0g) s[nf][1] = -1e30f;
                    if (kc > r1g)     s[nf][2] = -1e30f;
                    if (kc + 1 > r1g) s[nf][3] = -1e30f;
                }
            }

            // ---- online softmax (intra-quad) ----
            float m0l = -INFINITY, m1l = -INFINITY;
#pragma unroll
            for (int nf = 0; nf < 8; nf++) {
                m0l = fmaxf(m0l, fmaxf(s[nf][0], s[nf][1]));
                m1l = fmaxf(m1l, fmaxf(s[nf][2], s[nf][3]));
            }
            m0l = fmaxf(m0l, __shfl_xor_sync(0xffffffffu, m0l, 1));
            m0l = fmaxf(m0l, __shfl_xor_sync(0xffffffffu, m0l, 2));
            m1l = fmaxf(m1l, __shfl_xor_sync(0xffffffffu, m1l, 1));
            m1l = fmaxf(m1l, __shfl_xor_sync(0xffffffffu, m1l, 2));
            const float m0n = fmaxf(m0, m0l), m1n = fmaxf(m1, m1l);
            const float a0 = exp2f((m0 - m0n) * L2E);
            const float a1 = exp2f((m1 - m1n) * L2E);
            m0 = m0n; m1 = m1n;

            float sum0 = 0.f, sum1 = 0.f;
#pragma unroll
            for (int nf = 0; nf < 8; nf++) {
                s[nf][0] = exp2f((s[nf][0] - m0n) * L2E); sum0 += s[nf][0];
                s[nf][1] = exp2f((s[nf][1] - m0n) * L2E); sum0 += s[nf][1];
                s[nf][2] = exp2f((s[nf][2] - m1n) * L2E); sum1 += s[nf][2];
                s[nf][3] = exp2f((s[nf][3] - m1n) * L2E); sum1 += s[nf][3];
            }
            sum0 += __shfl_xor_sync(0xffffffffu, sum0, 1);
            sum0 += __shfl_xor_sync(0xffffffffu, sum0, 2);
            sum1 += __shfl_xor_sync(0xffffffffu, sum1, 1);
            sum1 += __shfl_xor_sync(0xffffffffu, sum1, 2);
            l0 = l0 * a0 + sum0;
            l1 = l1 * a1 + sum1;

#pragma unroll
            for (int nf = 0; nf < 16; nf++) {
                o[nf][0] *= a0; o[nf][1] *= a0;
                o[nf][2] *= a1; o[nf][3] *= a1;
            }

            // ---- O += P V (3 chains) ----
            const uint32_t vb = kb + 2 * FL_TILE;
#pragma unroll
            for (int kf2 = 0; kf2 < 4; kf2++) {
                uint32_t ah[4], al[4];
#pragma unroll
                for (int q2 = 0; q2 < 2; q2++) {       // two S n-frags per kf2
                    const float* sp = s[2 * kf2 + q2];
#pragma unroll
                    for (int rr = 0; rr < 2; rr++) {   // rows r0 / r1
                        const float pe = sp[rr * 2], po = sp[rr * 2 + 1];
                        const uint32_t ph = pack_bf16x2(pe, po);
                        const float rle = pe - __uint_as_float(ph << 16);
                        const float rlo = po - __uint_as_float(ph & 0xffff0000u);
                        ah[q2 * 2 + rr] = ph;
                        al[q2 * 2 + rr] = pack_bf16x2(rle, rlo);
                    }
                }
#pragma unroll
                for (int nfp = 0; nfp < 8; nfp++) {
                    uint32_t vh4[4], vl4[4];
                    const uint32_t va = vb + (kf2 * 16 + vrow) * FL_ROWB + vcolb + nfp * 32;
                    ldsm4t(vh4, va);
                    ldsm4t(vl4, va + FL_TILE);
                    mma_bf16(o[2 * nfp], ah, vh4);
                    mma_bf16(o[2 * nfp], ah, vl4);
                    mma_bf16(o[2 * nfp], al, vh4);
                    mma_bf16(o[2 * nfp + 1], ah, vh4 + 2);
                    mma_bf16(o[2 * nfp + 1], ah, vl4 + 2);
                    mma_bf16(o[2 * nfp + 1], al, vh4 + 2);
                }
            }
        }
    }

    // ---- finalize ----
    const float il0 = 1.f / l0, il1 = 1.f / l1;
    const size_t yb = hb + (size_t)r0g * EMB + (lane & 3) * 2;
#pragma unroll
    for (int nf = 0; nf < 16; nf++) {
        *(float2*)(Y + yb + nf * 8) = make_float2(o[nf][0] * il0, o[nf][1] * il0);
        *(float2*)(Y + yb + (size_t)8 * EMB + nf * 8) =
            make_float2(o[nf][2] * il1, o[nf][3] * il1);
    }
}

// =====================================================================
// launch
// =====================================================================
extern "C" void kernel_launch(void* const* d_in, const int* in_sizes, int n_in,
                              void* d_out, int out_size)
{
    const float* x  = (const float*)d_in[0];
    const float* wq = (const float*)d_in[1];
    const float* wk = (const float*)d_in[2];
    const float* wv = (const float*)d_in[3];
    const float* wo = (const float*)d_in[4];
    float* out = (float*)d_out;

    float *gq, *gk, *gv, *gy;
    __nv_bfloat16 *ahi, *alo, *wthi, *wtlo, *qh, *ql, *kh, *kl, *vh, *vl;
    cudaGetSymbolAddress((void**)&gq, g_q);
    cudaGetSymbolAddress((void**)&gk, g_k);
    cudaGetSymbolAddress((void**)&gv, g_v);
    cudaGetSymbolAddress((void**)&gy, g_y);
    cudaGetSymbolAddress((void**)&ahi, g_ahi);
    cudaGetSymbolAddress((void**)&alo, g_alo);
    cudaGetSymbolAddress((void**)&wthi, g_wthi);
    cudaGetSymbolAddress((void**)&wtlo, g_wtlo);
    cudaGetSymbolAddress((void**)&qh, g_qh);
    cudaGetSymbolAddress((void**)&ql, g_ql);
    cudaGetSymbolAddress((void**)&kh, g_kh);
    cudaGetSymbolAddress((void**)&kl, g_kl);
    cudaGetSymbolAddress((void**)&vh, g_vh);
    cudaGetSymbolAddress((void**)&vl, g_vl);

    cudaFuncSetAttribute(mma_gemm_kernel,
                         cudaFuncAttributeMaxDynamicSharedMemorySize, GEMM_SMEM);
    cudaFuncSetAttribute(flash_mma_kernel,
                         cudaFuncAttributeMaxDynamicSharedMemorySize, FL_SMEM);

    const int n4 = (int)(ELEMS / 4);
    const dim3 sgrid((n4 + 255) / 256);
    const dim3 wgrid(EMB / 32, EMB / 32);
    const dim3 ggrid(EMB / BN, MROWS / BM);

    // split x
    split_kernel<<<sgrid, 256>>>(x, ahi, alo, n4);

    // QKV projections
    wsplit_kernel<<<wgrid, 256>>>(wq, wthi, wtlo);
    mma_gemm_kernel<<<ggrid, 256, GEMM_SMEM>>>(ahi, alo, wthi, wtlo, gq, MROWS, EMB, EMB);
    wsplit_kernel<<<wgrid, 256>>>(wk, wthi, wtlo);
    mma_gemm_kernel<<<ggrid, 256, GEMM_SMEM>>>(ahi, alo, wthi, wtlo, gk, MROWS, EMB, EMB);
    wsplit_kernel<<<wgrid, 256>>>(wv, wthi, wtlo);
    mma_gemm_kernel<<<ggrid, 256, GEMM_SMEM>>>(ahi, alo, wthi, wtlo, gv, MROWS, EMB, EMB);

    // RoPE + RMSNorm + split (scale folded into Q), V split
    dim3 rgrid(NHEAD, SEQ, BATCH);
    ropeprep_kernel<<<rgrid, 64>>>(gq, qh, ql, 0.08838834764831845f);
    ropeprep_kernel<<<rgrid, 64>>>(gk, kh, kl, 1.0f);
    split_kernel<<<sgrid, 256>>>(gv, vh, vl, n4);

    // flash attention (tensor cores)
    dim3 fgrid(SEQ / 128, NHEAD, BATCH);
    flash_mma_kernel<<<fgrid, 256, FL_SMEM>>>(qh, ql, kh, kl, vh, vl, gy);

    // out = y @ wo
    split_kernel<<<sgrid, 256>>>(gy, ahi, alo, n4);
    wsplit_kernel<<<wgrid, 256>>>(wo, wthi, wtlo);
    mma_gemm_kernel<<<ggrid, 256, GEMM_SMEM>>>(ahi, alo, wthi, wtlo, out, MROWS, EMB, EMB);
}

// round 5
// speedup vs baseline: 2.2350x; 1.0028x over previous
#include <cuda_runtime.h>
#include <cuda_bf16.h>
#include <math.h>
#include <stdint.h>

// ---------------- constants ----------------
#define BATCH 4
#define SEQ   2048
#define EMB   2048
#define NHEAD 16
#define HDIM  128
#define MROWS (BATCH*SEQ)               // 8192
#define ELEMS ((size_t)BATCH*SEQ*EMB)   // 16777216
#define L2E   1.4426950408889634f

// ---------------- scratch (device globals: allocation-free) ----------------
__device__ float g_q[ELEMS];
__device__ float g_k[ELEMS];
__device__ __nv_bfloat16 g_ahi[ELEMS];
__device__ __nv_bfloat16 g_alo[ELEMS];
__device__ __nv_bfloat16 g_wthi[(size_t)3*EMB*EMB];
__device__ __nv_bfloat16 g_wtlo[(size_t)3*EMB*EMB];
__device__ __nv_bfloat16 g_qh[ELEMS];
__device__ __nv_bfloat16 g_ql[ELEMS];
__device__ __nv_bfloat16 g_kh[ELEMS];
__device__ __nv_bfloat16 g_kl[ELEMS];
__device__ __nv_bfloat16 g_vh[ELEMS];
__device__ __nv_bfloat16 g_vl[ELEMS];

// =====================================================================
// PTX helpers (standard sm_80+ instructions; valid on plain sm_103)
// =====================================================================
__device__ __forceinline__ uint32_t smem_to_u32(const void* p) {
    uint32_t a;
    asm("{ .reg .u64 t; cvta.to.shared.u64 t, %1; cvt.u32.u64 %0, t; }"
        : "=r"(a) : "l"(p));
    return a;
}

__device__ __forceinline__ void ldsm4(uint32_t* r, uint32_t addr) {
    asm volatile("ldmatrix.sync.aligned.m8n8.x4.shared.b16 {%0,%1,%2,%3}, [%4];"
        : "=r"(r[0]), "=r"(r[1]), "=r"(r[2]), "=r"(r[3]) : "r"(addr));
}
__device__ __forceinline__ void ldsm4t(uint32_t* r, uint32_t addr) {
    asm volatile("ldmatrix.sync.aligned.m8n8.x4.trans.shared.b16 {%0,%1,%2,%3}, [%4];"
        : "=r"(r[0]), "=r"(r[1]), "=r"(r[2]), "=r"(r[3]) : "r"(addr));
}

__device__ __forceinline__ void mma_bf16(float* c, const uint32_t* a, const uint32_t* b) {
    asm volatile(
        "mma.sync.aligned.m16n8k16.row.col.f32.bf16.bf16.f32 "
        "{%0,%1,%2,%3}, {%4,%5,%6,%7}, {%8,%9}, {%0,%1,%2,%3};"
        : "+f"(c[0]), "+f"(c[1]), "+f"(c[2]), "+f"(c[3])
        : "r"(a[0]), "r"(a[1]), "r"(a[2]), "r"(a[3]), "r"(b[0]), "r"(b[1]));
}

// pack two f32 into bf16x2: lower half = first arg
__device__ __forceinline__ uint32_t pack_bf16x2(float lo, float hi) {
    uint32_t r;
    asm("cvt.rn.bf16x2.f32 %0, %1, %2;" : "=r"(r) : "f"(hi), "f"(lo));
    return r;
}

#define CP_ASYNC16(dst, src) \
    asm volatile("cp.async.cg.shared.global [%0], [%1], 16;" :: "r"(dst), "l"(src) : "memory")
#define CP_COMMIT() asm volatile("cp.async.commit_group;" ::: "memory")
#define CP_WAIT2()  asm volatile("cp.async.wait_group 2;" ::: "memory")
#define CP_WAIT1()  asm volatile("cp.async.wait_group 1;" ::: "memory")
#define CP_WAIT0()  asm volatile("cp.async.wait_group 0;" ::: "memory")

// =====================================================================
// split: fp32 -> bf16 hi + bf16 lo (residual)
// =====================================================================
__global__ __launch_bounds__(256) void split_kernel(
    const float* __restrict__ in,
    __nv_bfloat16* __restrict__ hi, __nv_bfloat16* __restrict__ lo, int n4)
{
    int i = blockIdx.x * 256 + threadIdx.x;
    if (i >= n4) return;
    float4 v = ((const float4*)in)[i];
    __nv_bfloat16 h0 = __float2bfloat16(v.x);
    __nv_bfloat16 h1 = __float2bfloat16(v.y);
    __nv_bfloat16 h2 = __float2bfloat16(v.z);
    __nv_bfloat16 h3 = __float2bfloat16(v.w);
    __nv_bfloat16 l0 = __float2bfloat16(v.x - __bfloat162float(h0));
    __nv_bfloat16 l1 = __float2bfloat16(v.y - __bfloat162float(h1));
    __nv_bfloat16 l2 = __float2bfloat16(v.z - __bfloat162float(h2));
    __nv_bfloat16 l3 = __float2bfloat16(v.w - __bfloat162float(h3));
    __nv_bfloat162* hp = (__nv_bfloat162*)(hi + 4 * (size_t)i);
    __nv_bfloat162* lp = (__nv_bfloat162*)(lo + 4 * (size_t)i);
    hp[0] = __nv_bfloat162(h0, h1); hp[1] = __nv_bfloat162(h2, h3);
    lp[0] = __nv_bfloat162(l0, l1); lp[1] = __nv_bfloat162(l2, l3);
}

// =====================================================================
// weight transpose + split: W[K][N] fp32 -> WT_hi/WT_lo[N][K] bf16
// =====================================================================
__global__ __launch_bounds__(256) void wsplit_kernel(
    const float* __restrict__ w,
    __nv_bfloat16* __restrict__ hi, __nv_bfloat16* __restrict__ lo)
{
    __shared__ float tile[32][33];
    int n0 = blockIdx.x * 32, k0 = blockIdx.y * 32;
    int tx = threadIdx.x & 31, ty = threadIdx.x >> 5;
#pragma unroll
    for (int i = 0; i < 32; i += 8)
        tile[ty + i][tx] = w[(size_t)(k0 + ty + i) * EMB + n0 + tx];
    __syncthreads();
#pragma unroll
    for (int i = 0; i < 32; i += 8) {
        float v = tile[tx][ty + i];
        __nv_bfloat16 h = __float2bfloat16(v);
        size_t o = (size_t)(n0 + ty + i) * EMB + k0 + tx;
        hi[o] = h;
        lo[o] = __float2bfloat16(v - __bfloat162float(h));
    }
}

// =====================================================================
// mma.sync GEMM: C = A * B^T, split bf16 3-chain, 3-stage cp.async.
// mode 0: write fp32 to c0 (row stride EMB), N arbitrary (WO GEMM).
// mode 1: QKV fused (N=6144): n<2048 -> q fp32, <4096 -> k fp32,
//         else V written directly as bf16 hi/lo (c2h/c2l).
// =====================================================================
#define BM 128
#define BN 128
#define BK 64
#define RSTRB 144
#define TILE_B (128 * RSTRB)
#define STG_B  (4 * TILE_B)       // 73728 bytes
#define GEMM_SMEM (3 * STG_B)     // 221184 bytes

__global__ __launch_bounds__(256) void mma_gemm_kernel(
    const __nv_bfloat16* __restrict__ Ahi, const __nv_bfloat16* __restrict__ Alo,
    const __nv_bfloat16* __restrict__ Bhi, const __nv_bfloat16* __restrict__ Blo,
    int K, int mode,
    float* __restrict__ c0, float* __restrict__ c1,
    __nv_bfloat16* __restrict__ c2h, __nv_bfloat16* __restrict__ c2l)
{
    extern __shared__ char smc[];
    const uint32_t sb = smem_to_u32(smc);
    const int t = threadIdx.x;
    const int lane = t & 31;
    const int wid = t >> 5;
    const int warp_m = wid >> 2;
    const int warp_n = wid & 3;
    const int row0 = blockIdx.y * BM;
    const int col0 = blockIdx.x * BN;

    float acc[4][4][4];
#pragma unroll
    for (int i = 0; i < 4; i++)
#pragma unroll
        for (int j = 0; j < 4; j++)
#pragma unroll
            for (int r = 0; r < 4; r++) acc[i][j][r] = 0.f;

    const __nv_bfloat16* gsrc[4] = {Ahi, Alo, Bhi, Blo};
    const int gro[4] = {row0, row0, col0, col0};

    auto load_stage = [&](int s, int k0) {
        const uint32_t base = sb + s * STG_B;
#pragma unroll
        for (int tile = 0; tile < 4; tile++) {
            const __nv_bfloat16* src = gsrc[tile];
            const int rb = gro[tile];
            const uint32_t tb = base + tile * TILE_B;
#pragma unroll
            for (int i = 0; i < 4; i++) {
                const int idx = t + i * 256;
                const int r = idx >> 3;
                const int c = idx & 7;
                CP_ASYNC16(tb + r * RSTRB + c * 16,
                           src + (size_t)(rb + r) * K + k0 + c * 8);
            }
        }
    };

    const int nIter = K / BK;
    load_stage(0, 0);
    CP_COMMIT();
    load_stage(1, BK);
    CP_COMMIT();

    int stage = 0;
    for (int it = 0; it < nIter; it++) {
        if (it + 2 < nIter) {
            load_stage((stage + 2) % 3, (it + 2) * BK);
            CP_COMMIT();
            CP_WAIT2();
        } else if (it + 1 < nIter) {
            CP_WAIT1();
        } else {
            CP_WAIT0();
        }
        __syncthreads();

        const uint32_t abase = sb + stage * STG_B;
        const int arow = warp_m * 64 + (lane & 15);
        const int brow = warp_n * 32 + ((lane >> 4) << 3) + (lane & 7);

#pragma unroll
        for (int ks = 0; ks < 4; ks++) {
            uint32_t ah[4][4], al[4][4], bh[2][4], bl[2][4];
            const uint32_t acol = ks * 32 + ((lane >> 4) << 4);
            const uint32_t bcol = ks * 32 + (((lane >> 3) & 1) << 4);
#pragma unroll
            for (int mf = 0; mf < 4; mf++) {
                const uint32_t ad = abase + (arow + mf * 16) * RSTRB + acol;
                ldsm4(ah[mf], ad);
                ldsm4(al[mf], ad + TILE_B);
            }
#pragma unroll
            for (int np = 0; np < 2; np++) {
                const uint32_t bd = abase + 2 * TILE_B + (brow + np * 16) * RSTRB + bcol;
                ldsm4(bh[np], bd);
                ldsm4(bl[np], bd + TILE_B);
            }
#pragma unroll
            for (int mf = 0; mf < 4; mf++) {
#pragma unroll
                for (int nf = 0; nf < 4; nf++) {
                    const uint32_t* bhp = &bh[nf >> 1][(nf & 1) * 2];
                    const uint32_t* blp = &bl[nf >> 1][(nf & 1) * 2];
                    mma_bf16(acc[mf][nf], ah[mf], bhp);
                    mma_bf16(acc[mf][nf], ah[mf], blp);
                    mma_bf16(acc[mf][nf], al[mf], bhp);
                }
            }
        }
        __syncthreads();
        stage = (stage + 1) % 3;
    }

    // ---- epilogue ----
    const int mbase = row0 + warp_m * 64 + (lane >> 2);
    const int nb = col0 + warp_n * 32 + (lane & 3) * 2;
#pragma unroll
    for (int mf = 0; mf < 4; mf++) {
#pragma unroll
        for (int nf = 0; nf < 4; nf++) {
            const int n = nb + nf * 8;
            const int m0 = mbase + mf * 16;
            const float* a = acc[mf][nf];
            if (mode == 0) {
                const size_t o0 = (size_t)m0 * EMB + n;
                *(float2*)(c0 + o0) = make_float2(a[0], a[1]);
                *(float2*)(c0 + o0 + 8 * EMB) = make_float2(a[2], a[3]);
            } else {
                const int which = n >> 11;
                const int nloc = n & 2047;
                const size_t o0 = (size_t)m0 * EMB + nloc;
                if (which == 0) {
                    *(float2*)(c0 + o0) = make_float2(a[0], a[1]);
                    *(float2*)(c0 + o0 + 8 * EMB) = make_float2(a[2], a[3]);
                } else if (which == 1) {
                    *(float2*)(c1 + o0) = make_float2(a[0], a[1]);
                    *(float2*)(c1 + o0 + 8 * EMB) = make_float2(a[2], a[3]);
                } else {
                    uint32_t h0 = pack_bf16x2(a[0], a[1]);
                    uint32_t h1 = pack_bf16x2(a[2], a[3]);
                    uint32_t l0 = pack_bf16x2(a[0] - __uint_as_float(h0 << 16),
                                              a[1] - __uint_as_float(h0 & 0xffff0000u));
                    uint32_t l1 = pack_bf16x2(a[2] - __uint_as_float(h1 << 16),
                                              a[3] - __uint_as_float(h1 & 0xffff0000u));
                    *(uint32_t*)(c2h + o0) = h0;
                    *(uint32_t*)(c2h + o0 + 8 * EMB) = h1;
                    *(uint32_t*)(c2l + o0) = l0;
                    *(uint32_t*)(c2l + o0 + 8 * EMB) = l1;
                }
            }
        }
    }
}

// =====================================================================
// RoPE + RMSNorm + scale + bf16 hi/lo split (fused prep for flash)
// =====================================================================
__global__ void ropeprep_kernel(const float* __restrict__ buf,
                                __nv_bfloat16* __restrict__ hi,
                                __nv_bfloat16* __restrict__ lo,
                                float outscale)
{
    const int h = blockIdx.x, tp = blockIdx.y, b = blockIdx.z;
    const int i = threadIdx.x;  // 0..63
    const size_t base = ((size_t)b * SEQ + tp) * EMB + (size_t)h * HDIM;

    float x1 = buf[base + i];
    float x2 = buf[base + 64 + i];

    double inv = exp(-((double)i / 64.0) * log(10000.0));
    double ang = (double)tp * inv;
    double sd, cd;
    sincos(ang, &sd, &cd);
    float c = (float)cd, s = (float)sd;

    float n1 = x1 * c - x2 * s;
    float n2 = x1 * s + x2 * c;

    float sq = n1 * n1 + n2 * n2;
#pragma unroll
    for (int o = 16; o > 0; o >>= 1)
        sq += __shfl_xor_sync(0xffffffffu, sq, o);

    __shared__ float partial[2];
    if ((i & 31) == 0) partial[i >> 5] = sq;
    __syncthreads();
    float tot = partial[0] + partial[1];
    float r = rsqrtf(tot * (1.0f / 128.0f) + 1.1920929e-07f) * outscale;

    float y1 = n1 * r, y2 = n2 * r;
    __nv_bfloat16 h1 = __float2bfloat16(y1);
    __nv_bfloat16 h2 = __float2bfloat16(y2);
    hi[base + i]      = h1;
    hi[base + 64 + i] = h2;
    lo[base + i]      = __float2bfloat16(y1 - __bfloat162float(h1));
    lo[base + 64 + i] = __float2bfloat16(y2 - __bfloat162float(h2));
}

// =====================================================================
// Flash attention on mma.sync bf16 (split hi/lo, 3 chains both GEMMs).
// Output written directly as bf16 hi/lo for the WO GEMM.
// =====================================================================
#define FL_STR  136
#define FL_ROWB (FL_STR*2)
#define FL_TILE (64*FL_ROWB)
#define FL_STG  (4*FL_TILE)
#define FL_QLO  (128*FL_ROWB)
#define FL_SMEM (3*FL_STG)

__global__ __launch_bounds__(256, 1) void flash_mma_kernel(
    const __nv_bfloat16* __restrict__ Qh, const __nv_bfloat16* __restrict__ Ql,
    const __nv_bfloat16* __restrict__ Kh, const __nv_bfloat16* __restrict__ Kl,
    const __nv_bfloat16* __restrict__ Vh, const __nv_bfloat16* __restrict__ Vl,
    __nv_bfloat16* __restrict__ Yh, __nv_bfloat16* __restrict__ Yl)
{
    extern __shared__ char smc[];
    const uint32_t sb = smem_to_u32(smc);
    const int t = threadIdx.x;
    const int lane = t & 31;
    const int w = t >> 5;
    const int qi = gridDim.x - 1 - blockIdx.x;
    const int h = blockIdx.y, b = blockIdx.z;
    const int qs = qi * 128;
    const size_t hb = ((size_t)b * SEQ) * EMB + (size_t)h * HDIM;

#pragma unroll
    for (int i = 0; i < 8; i++) {
        const int idx = t + i * 256;
        const int r = idx >> 4, c = idx & 15;
        const size_t g = hb + (size_t)(qs + r) * EMB + c * 8;
        CP_ASYNC16(sb + r * FL_ROWB + c * 16, Qh + g);
        CP_ASYNC16(sb + FL_QLO + r * FL_ROWB + c * 16, Ql + g);
    }
    CP_COMMIT();

    auto load_kv = [&](int s, int ks) {
        const uint32_t base = sb + FL_STG * (1 + s);
        const __nv_bfloat16* srcs[4] = {Kh, Kl, Vh, Vl};
#pragma unroll
        for (int tile = 0; tile < 4; tile++) {
#pragma unroll
            for (int i = 0; i < 4; i++) {
                const int idx = t + i * 256;
                const int r = idx >> 4, c = idx & 15;
                CP_ASYNC16(base + tile * FL_TILE + r * FL_ROWB + c * 16,
                           srcs[tile] + hb + (size_t)(ks + r) * EMB + c * 8);
            }
        }
    };

    load_kv(0, 0);
    CP_COMMIT();

    float m0 = -INFINITY, m1 = -INFINITY, l0 = 0.f, l1 = 0.f;
    float o[16][4];
#pragma unroll
    for (int i = 0; i < 16; i++)
#pragma unroll
        for (int j = 0; j < 4; j++) o[i][j] = 0.f;

    const uint32_t q_addr = sb + (w * 16 + (lane & 15)) * FL_ROWB + (lane >> 4) * 16;
    const int krow = (lane & 7) + ((lane >> 4) << 3);
    const uint32_t kcolb = ((lane >> 3) & 1) * 16;
    const int vrow = (lane & 7) + (((lane >> 3) & 1) << 3);
    const uint32_t vcolb = (lane >> 4) * 16;

    const int r0g = qs + w * 16 + (lane >> 2);
    const int r1g = r0g + 8;
    const int nkt = (qs + 128) / 64;

    for (int jt = 0; jt < nkt; jt++) {
        CP_WAIT0();
        __syncthreads();
        if (jt + 1 < nkt) { load_kv((jt + 1) & 1, (jt + 1) * 64); CP_COMMIT(); }

        const int ks = jt * 64;
        if (ks <= qs + w * 16 + 15) {
            const uint32_t kb = sb + FL_STG * (1 + (jt & 1));

            float s[8][4];
#pragma unroll
            for (int i = 0; i < 8; i++)
#pragma unroll
                for (int j = 0; j < 4; j++) s[i][j] = 0.f;

#pragma unroll
            for (int kf = 0; kf < 8; kf++) {
                uint32_t qa[4], qla[4];
                ldsm4(qa, q_addr + kf * 32);
                ldsm4(qla, q_addr + FL_QLO + kf * 32);
#pragma unroll
                for (int nfp = 0; nfp < 4; nfp++) {
                    uint32_t kh4[4], kl4[4];
                    const uint32_t ka = kb + (nfp * 16 + krow) * FL_ROWB + kcolb + kf * 32;
                    ldsm4(kh4, ka);
                    ldsm4(kl4, ka + FL_TILE);
                    mma_bf16(s[2 * nfp], qa, kh4);
                    mma_bf16(s[2 * nfp], qa, kl4);
                    mma_bf16(s[2 * nfp], qla, kh4);
                    mma_bf16(s[2 * nfp + 1], qa, kh4 + 2);
                    mma_bf16(s[2 * nfp + 1], qa, kl4 + 2);
                    mma_bf16(s[2 * nfp + 1], qla, kh4 + 2);
                }
            }

            if (ks + 63 > r0g) {
#pragma unroll
                for (int nf = 0; nf < 8; nf++) {
                    const int kc = ks + nf * 8 + (lane & 3) * 2;
                    if (kc > r0g)     s[nf][0] = -1e30f;
                    if (kc + 1 > r0g) s[nf][1] = -1e30f;
                    if (kc > r1g)     s[nf][2] = -1e30f;
                    if (kc + 1 > r1g) s[nf][3] = -1e30f;
                }
            }

            float m0l = -INFINITY, m1l = -INFINITY;
#pragma unroll
            for (int nf = 0; nf < 8; nf++) {
                m0l = fmaxf(m0l, fmaxf(s[nf][0], s[nf][1]));
                m1l = fmaxf(m1l, fmaxf(s[nf][2], s[nf][3]));
            }
            m0l = fmaxf(m0l, __shfl_xor_sync(0xffffffffu, m0l, 1));
            m0l = fmaxf(m0l, __shfl_xor_sync(0xffffffffu, m0l, 2));
            m1l = fmaxf(m1l, __shfl_xor_sync(0xffffffffu, m1l, 1));
            m1l = fmaxf(m1l, __shfl_xor_sync(0xffffffffu, m1l, 2));
            const float m0n = fmaxf(m0, m0l), m1n = fmaxf(m1, m1l);
            const float a0 = exp2f((m0 - m0n) * L2E);
            const float a1 = exp2f((m1 - m1n) * L2E);
            m0 = m0n; m1 = m1n;

            float sum0 = 0.f, sum1 = 0.f;
#pragma unroll
            for (int nf = 0; nf < 8; nf++) {
                s[nf][0] = exp2f((s[nf][0] - m0n) * L2E); sum0 += s[nf][0];
                s[nf][1] = exp2f((s[nf][1] - m0n) * L2E); sum0 += s[nf][1];
                s[nf][2] = exp2f((s[nf][2] - m1n) * L2E); sum1 += s[nf][2];
                s[nf][3] = exp2f((s[nf][3] - m1n) * L2E); sum1 += s[nf][3];
            }
            sum0 += __shfl_xor_sync(0xffffffffu, sum0, 1);
            sum0 += __shfl_xor_sync(0xffffffffu, sum0, 2);
            sum1 += __shfl_xor_sync(0xffffffffu, sum1, 1);
            sum1 += __shfl_xor_sync(0xffffffffu, sum1, 2);
            l0 = l0 * a0 + sum0;
            l1 = l1 * a1 + sum1;

#pragma unroll
            for (int nf = 0; nf < 16; nf++) {
                o[nf][0] *= a0; o[nf][1] *= a0;
                o[nf][2] *= a1; o[nf][3] *= a1;
            }

            const uint32_t vb = kb + 2 * FL_TILE;
#pragma unroll
            for (int kf2 = 0; kf2 < 4; kf2++) {
                uint32_t ah[4], al[4];
#pragma unroll
                for (int q2 = 0; q2 < 2; q2++) {
                    const float* sp = s[2 * kf2 + q2];
#pragma unroll
                    for (int rr = 0; rr < 2; rr++) {
                        const float pe = sp[rr * 2], po = sp[rr * 2 + 1];
                        const uint32_t ph = pack_bf16x2(pe, po);
                        const float rle = pe - __uint_as_float(ph << 16);
                        const float rlo = po - __uint_as_float(ph & 0xffff0000u);
                        ah[q2 * 2 + rr] = ph;
                        al[q2 * 2 + rr] = pack_bf16x2(rle, rlo);
                    }
                }
#pragma unroll
                for (int nfp = 0; nfp < 8; nfp++) {
                    uint32_t vh4[4], vl4[4];
                    const uint32_t va = vb + (kf2 * 16 + vrow) * FL_ROWB + vcolb + nfp * 32;
                    ldsm4t(vh4, va);
                    ldsm4t(vl4, va + FL_TILE);
                    mma_bf16(o[2 * nfp], ah, vh4);
                    mma_bf16(o[2 * nfp], ah, vl4);
                    mma_bf16(o[2 * nfp], al, vh4);
                    mma_bf16(o[2 * nfp + 1], ah, vh4 + 2);
                    mma_bf16(o[2 * nfp + 1], ah, vl4 + 2);
                    mma_bf16(o[2 * nfp + 1], al, vh4 + 2);
                }
            }
        }
    }

    // ---- finalize: write bf16 hi/lo directly ----
    const float il0 = 1.f / l0, il1 = 1.f / l1;
    const size_t yb = hb + (size_t)r0g * EMB + (lane & 3) * 2;
#pragma unroll
    for (int nf = 0; nf < 16; nf++) {
        const float a0v = o[nf][0] * il0, a1v = o[nf][1] * il0;
        const float b0v = o[nf][2] * il1, b1v = o[nf][3] * il1;
        const uint32_t h0 = pack_bf16x2(a0v, a1v);
        const uint32_t h1 = pack_bf16x2(b0v, b1v);
        const uint32_t q0 = pack_bf16x2(a0v - __uint_as_float(h0 << 16),
                                        a1v - __uint_as_float(h0 & 0xffff0000u));
        const uint32_t q1 = pack_bf16x2(b0v - __uint_as_float(h1 << 16),
                                        b1v - __uint_as_float(h1 & 0xffff0000u));
        *(uint32_t*)(Yh + yb + nf * 8) = h0;
        *(uint32_t*)(Yl + yb + nf * 8) = q0;
        *(uint32_t*)(Yh + yb + (size_t)8 * EMB + nf * 8) = h1;
        *(uint32_t*)(Yl + yb + (size_t)8 * EMB + nf * 8) = q1;
    }
}

// =====================================================================
// launch
// =====================================================================
extern "C" void kernel_launch(void* const* d_in, const int* in_sizes, int n_in,
                              void* d_out, int out_size)
{
    const float* x  = (const float*)d_in[0];
    const float* wq = (const float*)d_in[1];
    const float* wk = (const float*)d_in[2];
    const float* wv = (const float*)d_in[3];
    const float* wo = (const float*)d_in[4];
    float* out = (float*)d_out;

    float *gq, *gk;
    __nv_bfloat16 *ahi, *alo, *wthi, *wtlo, *qh, *ql, *kh, *kl, *vh, *vl;
    cudaGetSymbolAddress((void**)&gq, g_q);
    cudaGetSymbolAddress((void**)&gk, g_k);
    cudaGetSymbolAddress((void**)&ahi, g_ahi);
    cudaGetSymbolAddress((void**)&alo, g_alo);
    cudaGetSymbolAddress((void**)&wthi, g_wthi);
    cudaGetSymbolAddress((void**)&wtlo, g_wtlo);
    cudaGetSymbolAddress((void**)&qh, g_qh);
    cudaGetSymbolAddress((void**)&ql, g_ql);
    cudaGetSymbolAddress((void**)&kh, g_kh);
    cudaGetSymbolAddress((void**)&kl, g_kl);
    cudaGetSymbolAddress((void**)&vh, g_vh);
    cudaGetSymbolAddress((void**)&vl, g_vl);

    cudaFuncSetAttribute(mma_gemm_kernel,
                         cudaFuncAttributeMaxDynamicSharedMemorySize, GEMM_SMEM);
    cudaFuncSetAttribute(flash_mma_kernel,
                         cudaFuncAttributeMaxDynamicSharedMemorySize, FL_SMEM);

    const int n4 = (int)(ELEMS / 4);
    const dim3 sgrid((n4 + 255) / 256);
    const dim3 wgrid(EMB / 32, EMB / 32);
    const size_t WSZ = (size_t)EMB * EMB;

    // split x -> ahi/alo
    split_kernel<<<sgrid, 256>>>(x, ahi, alo, n4);

    // transpose+split all three projection weights into one [6144, 2048] B
    wsplit_kernel<<<wgrid, 256>>>(wq, wthi, wtlo);
    wsplit_kernel<<<wgrid, 256>>>(wk, wthi + WSZ, wtlo + WSZ);
    wsplit_kernel<<<wgrid, 256>>>(wv, wthi + 2 * WSZ, wtlo + 2 * WSZ);

    // fused QKV GEMM: q,k fp32; v directly bf16 hi/lo
    dim3 qkvgrid(3 * EMB / BN, MROWS / BM);   // (48, 64)
    mma_gemm_kernel<<<qkvgrid, 256, GEMM_SMEM>>>(
        ahi, alo, wthi, wtlo, EMB, 1, gq, gk, vh, vl);

    // RoPE + RMSNorm + split (scale folded into Q)
    dim3 rgrid(NHEAD, SEQ, BATCH);
    ropeprep_kernel<<<rgrid, 64>>>(gq, qh, ql, 0.08838834764831845f);
    ropeprep_kernel<<<rgrid, 64>>>(gk, kh, kl, 1.0f);

    // WO weight prep (reuses slot 0 after QKV GEMM consumed it)
    wsplit_kernel<<<wgrid, 256>>>(wo, wthi, wtlo);

    // flash attention -> writes ahi/alo (bf16 hi/lo) directly
    dim3 fgrid(SEQ / 128, NHEAD, BATCH);
    flash_mma_kernel<<<fgrid, 256, FL_SMEM>>>(qh, ql, kh, kl, vh, vl, ahi, alo);

    // out = y @ wo
    dim3 ogrid(EMB / BN, MROWS / BM);
    mma_gemm_kernel<<<ogrid, 256, GEMM_SMEM>>>(
        ahi, alo, wthi, wtlo, EMB, 0, out, nullptr, nullptr, nullptr);
}

// round 6
// speedup vs baseline: 3.8987x; 1.7444x over previous
#include <cuda_runtime.h>
#include <cuda_bf16.h>
#include <math.h>
#include <stdint.h>

// ---------------- constants ----------------
#define BATCH 4
#define SEQ   2048
#define EMB   2048
#define NHEAD 16
#define HDIM  128
#define MROWS (BATCH*SEQ)               // 8192
#define ELEMS ((size_t)BATCH*SEQ*EMB)   // 16777216
#define L2E   1.4426950408889634f

// ---------------- scratch (device globals: allocation-free) ----------------
__device__ float g_q[ELEMS];
__device__ float g_k[ELEMS];
__device__ __nv_bfloat16 g_ahi[ELEMS];
__device__ __nv_bfloat16 g_alo[ELEMS];
__device__ __nv_bfloat16 g_wthi[(size_t)4*EMB*EMB];
__device__ __nv_bfloat16 g_wtlo[(size_t)4*EMB*EMB];
__device__ __nv_bfloat16 g_qh[ELEMS];
__device__ __nv_bfloat16 g_ql[ELEMS];
__device__ __nv_bfloat16 g_kh[ELEMS];
__device__ __nv_bfloat16 g_kl[ELEMS];
__device__ __nv_bfloat16 g_vh[ELEMS];
__device__ __nv_bfloat16 g_vl[ELEMS];
__device__ float g_cos[SEQ*64];
__device__ float g_sin[SEQ*64];

// =====================================================================
// PTX helpers (standard sm_80+ instructions; valid on plain sm_103)
// =====================================================================
__device__ __forceinline__ uint32_t smem_to_u32(const void* p) {
    uint32_t a;
    asm("{ .reg .u64 t; cvta.to.shared.u64 t, %1; cvt.u32.u64 %0, t; }"
        : "=r"(a) : "l"(p));
    return a;
}

__device__ __forceinline__ void ldsm4(uint32_t* r, uint32_t addr) {
    asm volatile("ldmatrix.sync.aligned.m8n8.x4.shared.b16 {%0,%1,%2,%3}, [%4];"
        : "=r"(r[0]), "=r"(r[1]), "=r"(r[2]), "=r"(r[3]) : "r"(addr));
}
__device__ __forceinline__ void ldsm4t(uint32_t* r, uint32_t addr) {
    asm volatile("ldmatrix.sync.aligned.m8n8.x4.trans.shared.b16 {%0,%1,%2,%3}, [%4];"
        : "=r"(r[0]), "=r"(r[1]), "=r"(r[2]), "=r"(r[3]) : "r"(addr));
}

__device__ __forceinline__ void mma_bf16(float* c, const uint32_t* a, const uint32_t* b) {
    asm volatile(
        "mma.sync.aligned.m16n8k16.row.col.f32.bf16.bf16.f32 "
        "{%0,%1,%2,%3}, {%4,%5,%6,%7}, {%8,%9}, {%0,%1,%2,%3};"
        : "+f"(c[0]), "+f"(c[1]), "+f"(c[2]), "+f"(c[3])
        : "r"(a[0]), "r"(a[1]), "r"(a[2]), "r"(a[3]), "r"(b[0]), "r"(b[1]));
}

__device__ __forceinline__ uint32_t pack_bf16x2(float lo, float hi) {
    uint32_t r;
    asm("cvt.rn.bf16x2.f32 %0, %1, %2;" : "=r"(r) : "f"(hi), "f"(lo));
    return r;
}

#define CP_ASYNC16(dst, src) \
    asm volatile("cp.async.cg.shared.global [%0], [%1], 16;" :: "r"(dst), "l"(src) : "memory")
#define CP_COMMIT() asm volatile("cp.async.commit_group;" ::: "memory")
#define CP_WAIT1()  asm volatile("cp.async.wait_group 1;" ::: "memory")
#define CP_WAIT0()  asm volatile("cp.async.wait_group 0;" ::: "memory")

// =====================================================================
// split: fp32 -> bf16 hi + bf16 lo (residual)
// =====================================================================
__global__ __launch_bounds__(256) void split_kernel(
    const float* __restrict__ in,
    __nv_bfloat16* __restrict__ hi, __nv_bfloat16* __restrict__ lo, int n4)
{
    int i = blockIdx.x * 256 + threadIdx.x;
    if (i >= n4) return;
    float4 v = ((const float4*)in)[i];
    __nv_bfloat16 h0 = __float2bfloat16(v.x);
    __nv_bfloat16 h1 = __float2bfloat16(v.y);
    __nv_bfloat16 h2 = __float2bfloat16(v.z);
    __nv_bfloat16 h3 = __float2bfloat16(v.w);
    __nv_bfloat16 l0 = __float2bfloat16(v.x - __bfloat162float(h0));
    __nv_bfloat16 l1 = __float2bfloat16(v.y - __bfloat162float(h1));
    __nv_bfloat16 l2 = __float2bfloat16(v.z - __bfloat162float(h2));
    __nv_bfloat16 l3 = __float2bfloat16(v.w - __bfloat162float(h3));
    __nv_bfloat162* hp = (__nv_bfloat162*)(hi + 4 * (size_t)i);
    __nv_bfloat162* lp = (__nv_bfloat162*)(lo + 4 * (size_t)i);
    hp[0] = __nv_bfloat162(h0, h1); hp[1] = __nv_bfloat162(h2, h3);
    lp[0] = __nv_bfloat162(l0, l1); lp[1] = __nv_bfloat162(l2, l3);
}

// =====================================================================
// weight transpose + split: W[K][N] fp32 -> WT_hi/WT_lo[N][K] bf16
// =====================================================================
__global__ __launch_bounds__(256) void wsplit_kernel(
    const float* __restrict__ w,
    __nv_bfloat16* __restrict__ hi, __nv_bfloat16* __restrict__ lo)
{
    __shared__ float tile[32][33];
    int n0 = blockIdx.x * 32, k0 = blockIdx.y * 32;
    int tx = threadIdx.x & 31, ty = threadIdx.x >> 5;
#pragma unroll
    for (int i = 0; i < 32; i += 8)
        tile[ty + i][tx] = w[(size_t)(k0 + ty + i) * EMB + n0 + tx];
    __syncthreads();
#pragma unroll
    for (int i = 0; i < 32; i += 8) {
        float v = tile[tx][ty + i];
        __nv_bfloat16 h = __float2bfloat16(v);
        size_t o = (size_t)(n0 + ty + i) * EMB + k0 + tx;
        hi[o] = h;
        lo[o] = __float2bfloat16(v - __bfloat162float(h));
    }
}

// =====================================================================
// RoPE table precompute (double precision, once)
// =====================================================================
__global__ __launch_bounds__(256) void rope_table_kernel(
    float* __restrict__ ct, float* __restrict__ st)
{
    const int idx = blockIdx.x * 256 + threadIdx.x;   // 0 .. SEQ*64-1
    if (idx >= SEQ * 64) return;
    const int tp = idx >> 6, i = idx & 63;
    double inv = exp(-((double)i / 64.0) * log(10000.0));
    double ang = (double)tp * inv;
    double sd, cd;
    sincos(ang, &sd, &cd);
    ct[idx] = (float)cd;
    st[idx] = (float)sd;
}

// =====================================================================
// mma.sync GEMM: C = A * B^T, split bf16 3-chain, 2-stage cp.async.
// Block tile 128x256x64, 8 warps (2 x 4), warp tile 64x64.
// mode 0: write fp32 to c0 (row stride EMB).
// mode 1: QKV fused (N=6144): n<2048 -> c0 fp32, <4096 -> c1 fp32,
//         else V written directly as bf16 hi/lo (c2h/c2l).
// =====================================================================
#define BM 128
#define BN 256
#define BK 64
#define RSTRB 144
#define TA (128 * RSTRB)          // 18432
#define TB (256 * RSTRB)          // 36864
#define STG_B (2*TA + 2*TB)       // 110592
#define GEMM_SMEM (2 * STG_B)     // 221184

__global__ __launch_bounds__(256) void mma_gemm_kernel(
    const __nv_bfloat16* __restrict__ Ahi, const __nv_bfloat16* __restrict__ Alo,
    const __nv_bfloat16* __restrict__ Bhi, const __nv_bfloat16* __restrict__ Blo,
    int K, int mode,
    float* __restrict__ c0, float* __restrict__ c1,
    __nv_bfloat16* __restrict__ c2h, __nv_bfloat16* __restrict__ c2l)
{
    extern __shared__ char smc[];
    const uint32_t sb = smem_to_u32(smc);
    const int t = threadIdx.x;
    const int lane = t & 31;
    const int wid = t >> 5;
    const int warp_m = wid & 1;      // 0..1
    const int warp_n = wid >> 1;     // 0..3
    const int row0 = blockIdx.y * BM;
    const int col0 = blockIdx.x * BN;

    float acc[4][8][4];
#pragma unroll
    for (int i = 0; i < 4; i++)
#pragma unroll
        for (int j = 0; j < 8; j++)
#pragma unroll
            for (int r = 0; r < 4; r++) acc[i][j][r] = 0.f;

    auto load_stage = [&](int s, int k0) {
        const uint32_t base = sb + s * STG_B;
        // A hi/lo: 128 rows x 8 chunks
#pragma unroll
        for (int i = 0; i < 4; i++) {
            const int idx = t + i * 256;
            const int r = idx >> 3, c = idx & 7;
            const size_t g = (size_t)(row0 + r) * K + k0 + c * 8;
            const uint32_t d = base + r * RSTRB + c * 16;
            CP_ASYNC16(d, Ahi + g);
            CP_ASYNC16(d + TA, Alo + g);
        }
        // B hi/lo: 256 rows x 8 chunks
#pragma unroll
        for (int i = 0; i < 8; i++) {
            const int idx = t + i * 256;
            const int r = idx >> 3, c = idx & 7;
            const size_t g = (size_t)(col0 + r) * K + k0 + c * 8;
            const uint32_t d = base + 2 * TA + r * RSTRB + c * 16;
            CP_ASYNC16(d, Bhi + g);
            CP_ASYNC16(d + TB, Blo + g);
        }
    };

    const int nIter = K / BK;
    load_stage(0, 0);
    CP_COMMIT();

    for (int it = 0; it < nIter; it++) {
        if (it + 1 < nIter) {
            load_stage((it + 1) & 1, (it + 1) * BK);
            CP_COMMIT();
            CP_WAIT1();
        } else {
            CP_WAIT0();
        }
        __syncthreads();

        const uint32_t abase = sb + (it & 1) * STG_B;
        const uint32_t bbase = abase + 2 * TA;
        const int arow = warp_m * 64 + (lane & 15);
        const int brow = warp_n * 64 + ((lane >> 4) << 3) + (lane & 7);

#pragma unroll
        for (int ks = 0; ks < 4; ks++) {
            uint32_t ah[4][4], al[4][4], bh[4][4], bl[4][4];
            const uint32_t acol = ks * 32 + ((lane >> 4) << 4);
            const uint32_t bcol = ks * 32 + (((lane >> 3) & 1) << 4);
#pragma unroll
            for (int mf = 0; mf < 4; mf++) {
                const uint32_t ad = abase + (arow + mf * 16) * RSTRB + acol;
                ldsm4(ah[mf], ad);
                ldsm4(al[mf], ad + TA);
            }
#pragma unroll
            for (int bf = 0; bf < 4; bf++) {
                const uint32_t bd = bbase + (brow + bf * 16) * RSTRB + bcol;
                ldsm4(bh[bf], bd);
                ldsm4(bl[bf], bd + TB);
            }
#pragma unroll
            for (int mf = 0; mf < 4; mf++) {
#pragma unroll
                for (int nf = 0; nf < 8; nf++) {
                    const uint32_t* bhp = &bh[nf >> 1][(nf & 1) * 2];
                    const uint32_t* blp = &bl[nf >> 1][(nf & 1) * 2];
                    mma_bf16(acc[mf][nf], ah[mf], bhp);
                    mma_bf16(acc[mf][nf], ah[mf], blp);
                    mma_bf16(acc[mf][nf], al[mf], bhp);
                }
            }
        }
        __syncthreads();
    }

    // ---- epilogue ----
    const int mbase = row0 + warp_m * 64 + (lane >> 2);
    const int nb = col0 + warp_n * 64 + (lane & 3) * 2;
#pragma unroll
    for (int mf = 0; mf < 4; mf++) {
#pragma unroll
        for (int nf = 0; nf < 8; nf++) {
            const int n = nb + nf * 8;
            const int m0 = mbase + mf * 16;
            const float* a = acc[mf][nf];
            if (mode == 0) {
                const size_t o0 = (size_t)m0 * EMB + n;
                *(float2*)(c0 + o0) = make_float2(a[0], a[1]);
                *(float2*)(c0 + o0 + 8 * EMB) = make_float2(a[2], a[3]);
            } else {
                const int which = n >> 11;
                const int nloc = n & 2047;
                const size_t o0 = (size_t)m0 * EMB + nloc;
                if (which == 0) {
                    *(float2*)(c0 + o0) = make_float2(a[0], a[1]);
                    *(float2*)(c0 + o0 + 8 * EMB) = make_float2(a[2], a[3]);
                } else if (which == 1) {
                    *(float2*)(c1 + o0) = make_float2(a[0], a[1]);
                    *(float2*)(c1 + o0 + 8 * EMB) = make_float2(a[2], a[3]);
                } else {
                    uint32_t h0 = pack_bf16x2(a[0], a[1]);
                    uint32_t h1 = pack_bf16x2(a[2], a[3]);
                    uint32_t l0 = pack_bf16x2(a[0] - __uint_as_float(h0 << 16),
                                              a[1] - __uint_as_float(h0 & 0xffff0000u));
                    uint32_t l1 = pack_bf16x2(a[2] - __uint_as_float(h1 << 16),
                                              a[3] - __uint_as_float(h1 & 0xffff0000u));
                    *(uint32_t*)(c2h + o0) = h0;
                    *(uint32_t*)(c2h + o0 + 8 * EMB) = h1;
                    *(uint32_t*)(c2l + o0) = l0;
                    *(uint32_t*)(c2l + o0 + 8 * EMB) = l1;
                }
            }
        }
    }
}

// =====================================================================
// RoPE + RMSNorm + scale + bf16 hi/lo split (table-based, pure fp32)
// =====================================================================
__global__ void ropeprep_kernel(const float* __restrict__ buf,
                                const float* __restrict__ ct,
                                const float* __restrict__ st,
                                __nv_bfloat16* __restrict__ hi,
                                __nv_bfloat16* __restrict__ lo,
                                float outscale)
{
    const int h = blockIdx.x, tp = blockIdx.y, b = blockIdx.z;
    const int i = threadIdx.x;  // 0..63
    const size_t base = ((size_t)b * SEQ + tp) * EMB + (size_t)h * HDIM;

    float x1 = buf[base + i];
    float x2 = buf[base + 64 + i];

    const float c = ct[tp * 64 + i];
    const float s = st[tp * 64 + i];

    float n1 = x1 * c - x2 * s;
    float n2 = x1 * s + x2 * c;

    float sq = n1 * n1 + n2 * n2;
#pragma unroll
    for (int o = 16; o > 0; o >>= 1)
        sq += __shfl_xor_sync(0xffffffffu, sq, o);

    __shared__ float partial[2];
    if ((i & 31) == 0) partial[i >> 5] = sq;
    __syncthreads();
    float tot = partial[0] + partial[1];
    float r = rsqrtf(tot * (1.0f / 128.0f) + 1.1920929e-07f) * outscale;

    float y1 = n1 * r, y2 = n2 * r;
    __nv_bfloat16 h1 = __float2bfloat16(y1);
    __nv_bfloat16 h2 = __float2bfloat16(y2);
    hi[base + i]      = h1;
    hi[base + 64 + i] = h2;
    lo[base + i]      = __float2bfloat16(y1 - __bfloat162float(h1));
    lo[base + 64 + i] = __float2bfloat16(y2 - __bfloat162float(h2));
}

// =====================================================================
// Flash attention on mma.sync bf16 (split hi/lo, 3 chains both GEMMs).
// Output written directly as bf16 hi/lo for the WO GEMM.
// =====================================================================
#define FL_STR  136
#define FL_ROWB (FL_STR*2)
#define FL_TILE (64*FL_ROWB)
#define FL_STG  (4*FL_TILE)
#define FL_QLO  (128*FL_ROWB)
#define FL_SMEM (3*FL_STG)

__global__ __launch_bounds__(256, 1) void flash_mma_kernel(
    const __nv_bfloat16* __restrict__ Qh, const __nv_bfloat16* __restrict__ Ql,
    const __nv_bfloat16* __restrict__ Kh, const __nv_bfloat16* __restrict__ Kl,
    const __nv_bfloat16* __restrict__ Vh, const __nv_bfloat16* __restrict__ Vl,
    __nv_bfloat16* __restrict__ Yh, __nv_bfloat16* __restrict__ Yl)
{
    extern __shared__ char smc[];
    const uint32_t sb = smem_to_u32(smc);
    const int t = threadIdx.x;
    const int lane = t & 31;
    const int w = t >> 5;
    const int qi = gridDim.x - 1 - blockIdx.x;
    const int h = blockIdx.y, b = blockIdx.z;
    const int qs = qi * 128;
    const size_t hb = ((size_t)b * SEQ) * EMB + (size_t)h * HDIM;

#pragma unroll
    for (int i = 0; i < 8; i++) {
        const int idx = t + i * 256;
        const int r = idx >> 4, c = idx & 15;
        const size_t g = hb + (size_t)(qs + r) * EMB + c * 8;
        CP_ASYNC16(sb + r * FL_ROWB + c * 16, Qh + g);
        CP_ASYNC16(sb + FL_QLO + r * FL_ROWB + c * 16, Ql + g);
    }
    CP_COMMIT();

    auto load_kv = [&](int s, int ks) {
        const uint32_t base = sb + FL_STG * (1 + s);
        const __nv_bfloat16* srcs[4] = {Kh, Kl, Vh, Vl};
#pragma unroll
        for (int tile = 0; tile < 4; tile++) {
#pragma unroll
            for (int i = 0; i < 4; i++) {
                const int idx = t + i * 256;
                const int r = idx >> 4, c = idx & 15;
                CP_ASYNC16(base + tile * FL_TILE + r * FL_ROWB + c * 16,
                           srcs[tile] + hb + (size_t)(ks + r) * EMB + c * 8);
            }
        }
    };

    load_kv(0, 0);
    CP_COMMIT();

    float m0 = -INFINITY, m1 = -INFINITY, l0 = 0.f, l1 = 0.f;
    float o[16][4];
#pragma unroll
    for (int i = 0; i < 16; i++)
#pragma unroll
        for (int j = 0; j < 4; j++) o[i][j] = 0.f;

    const uint32_t q_addr = sb + (w * 16 + (lane & 15)) * FL_ROWB + (lane >> 4) * 16;
    const int krow = (lane & 7) + ((lane >> 4) << 3);
    const uint32_t kcolb = ((lane >> 3) & 1) * 16;
    const int vrow = (lane & 7) + (((lane >> 3) & 1) << 3);
    const uint32_t vcolb = (lane >> 4) * 16;

    const int r0g = qs + w * 16 + (lane >> 2);
    const int r1g = r0g + 8;
    const int nkt = (qs + 128) / 64;

    for (int jt = 0; jt < nkt; jt++) {
        CP_WAIT0();
        __syncthreads();
        if (jt + 1 < nkt) { load_kv((jt + 1) & 1, (jt + 1) * 64); CP_COMMIT(); }

        const int ks = jt * 64;
        if (ks <= qs + w * 16 + 15) {
            const uint32_t kb = sb + FL_STG * (1 + (jt & 1));

            float s[8][4];
#pragma unroll
            for (int i = 0; i < 8; i++)
#pragma unroll
                for (int j = 0; j < 4; j++) s[i][j] = 0.f;

#pragma unroll
            for (int kf = 0; kf < 8; kf++) {
                uint32_t qa[4], qla[4];
                ldsm4(qa, q_addr + kf * 32);
                ldsm4(qla, q_addr + FL_QLO + kf * 32);
#pragma unroll
                for (int nfp = 0; nfp < 4; nfp++) {
                    uint32_t kh4[4], kl4[4];
                    const uint32_t ka = kb + (nfp * 16 + krow) * FL_ROWB + kcolb + kf * 32;
                    ldsm4(kh4, ka);
                    ldsm4(kl4, ka + FL_TILE);
                    mma_bf16(s[2 * nfp], qa, kh4);
                    mma_bf16(s[2 * nfp], qa, kl4);
                    mma_bf16(s[2 * nfp], qla, kh4);
                    mma_bf16(s[2 * nfp + 1], qa, kh4 + 2);
                    mma_bf16(s[2 * nfp + 1], qa, kl4 + 2);
                    mma_bf16(s[2 * nfp + 1], qla, kh4 + 2);
                }
            }

            if (ks + 63 > r0g) {
#pragma unroll
                for (int nf = 0; nf < 8; nf++) {
                    const int kc = ks + nf * 8 + (lane & 3) * 2;
                    if (kc > r0g)     s[nf][0] = -1e30f;
                    if (kc + 1 > r0g) s[nf][1] = -1e30f;
                    if (kc > r1g)     s[nf][2] = -1e30f;
                    if (kc + 1 > r1g) s[nf][3] = -1e30f;
                }
            }

            float m0l = -INFINITY, m1l = -INFINITY;
#pragma unroll
            for (int nf = 0; nf < 8; nf++) {
                m0l = fmaxf(m0l, fmaxf(s[nf][0], s[nf][1]));
                m1l = fmaxf(m1l, fmaxf(s[nf][2], s[nf][3]));
            }
            m0l = fmaxf(m0l, __shfl_xor_sync(0xffffffffu, m0l, 1));
            m0l = fmaxf(m0l, __shfl_xor_sync(0xffffffffu, m0l, 2));
            m1l = fmaxf(m1l, __shfl_xor_sync(0xffffffffu, m1l, 1));
            m1l = fmaxf(m1l, __shfl_xor_sync(0xffffffffu, m1l, 2));
            const float m0n = fmaxf(m0, m0l), m1n = fmaxf(m1, m1l);
            const float a0 = exp2f((m0 - m0n) * L2E);
            const float a1 = exp2f((m1 - m1n) * L2E);
            m0 = m0n; m1 = m1n;

            float sum0 = 0.f, sum1 = 0.f;
#pragma unroll
            for (int nf = 0; nf < 8; nf++) {
                s[nf][0] = exp2f((s[nf][0] - m0n) * L2E); sum0 += s[nf][0];
                s[nf][1] = exp2f((s[nf][1] - m0n) * L2E); sum0 += s[nf][1];
                s[nf][2] = exp2f((s[nf][2] - m1n) * L2E); sum1 += s[nf][2];
                s[nf][3] = exp2f((s[nf][3] - m1n) * L2E); sum1 += s[nf][3];
            }
            sum0 += __shfl_xor_sync(0xffffffffu, sum0, 1);
            sum0 += __shfl_xor_sync(0xffffffffu, sum0, 2);
            sum1 += __shfl_xor_sync(0xffffffffu, sum1, 1);
            sum1 += __shfl_xor_sync(0xffffffffu, sum1, 2);
            l0 = l0 * a0 + sum0;
            l1 = l1 * a1 + sum1;

#pragma unroll
            for (int nf = 0; nf < 16; nf++) {
                o[nf][0] *= a0; o[nf][1] *= a0;
                o[nf][2] *= a1; o[nf][3] *= a1;
            }

            const uint32_t vb = kb + 2 * FL_TILE;
#pragma unroll
            for (int kf2 = 0; kf2 < 4; kf2++) {
                uint32_t ah[4], al[4];
#pragma unroll
                for (int q2 = 0; q2 < 2; q2++) {
                    const float* sp = s[2 * kf2 + q2];
#pragma unroll
                    for (int rr = 0; rr < 2; rr++) {
                        const float pe = sp[rr * 2], po = sp[rr * 2 + 1];
                        const uint32_t ph = pack_bf16x2(pe, po);
                        const float rle = pe - __uint_as_float(ph << 16);
                        const float rlo = po - __uint_as_float(ph & 0xffff0000u);
                        ah[q2 * 2 + rr] = ph;
                        al[q2 * 2 + rr] = pack_bf16x2(rle, rlo);
                    }
                }
#pragma unroll
                for (int nfp = 0; nfp < 8; nfp++) {
                    uint32_t vh4[4], vl4[4];
                    const uint32_t va = vb + (kf2 * 16 + vrow) * FL_ROWB + vcolb + nfp * 32;
                    ldsm4t(vh4, va);
                    ldsm4t(vl4, va + FL_TILE);
                    mma_bf16(o[2 * nfp], ah, vh4);
                    mma_bf16(o[2 * nfp], ah, vl4);
                    mma_bf16(o[2 * nfp], al, vh4);
                    mma_bf16(o[2 * nfp + 1], ah, vh4 + 2);
                    mma_bf16(o[2 * nfp + 1], ah, vl4 + 2);
                    mma_bf16(o[2 * nfp + 1], al, vh4 + 2);
                }
            }
        }
    }

    const float il0 = 1.f / l0, il1 = 1.f / l1;
    const size_t yb = hb + (size_t)r0g * EMB + (lane & 3) * 2;
#pragma unroll
    for (int nf = 0; nf < 16; nf++) {
        const float a0v = o[nf][0] * il0, a1v = o[nf][1] * il0;
        const float b0v = o[nf][2] * il1, b1v = o[nf][3] * il1;
        const uint32_t h0 = pack_bf16x2(a0v, a1v);
        const uint32_t h1 = pack_bf16x2(b0v, b1v);
        const uint32_t q0 = pack_bf16x2(a0v - __uint_as_float(h0 << 16),
                                        a1v - __uint_as_float(h0 & 0xffff0000u));
        const uint32_t q1 = pack_bf16x2(b0v - __uint_as_float(h1 << 16),
                                        b1v - __uint_as_float(h1 & 0xffff0000u));
        *(uint32_t*)(Yh + yb + nf * 8) = h0;
        *(uint32_t*)(Yl + yb + nf * 8) = q0;
        *(uint32_t*)(Yh + yb + (size_t)8 * EMB + nf * 8) = h1;
        *(uint32_t*)(Yl + yb + (size_t)8 * EMB + nf * 8) = q1;
    }
}

// =====================================================================
// launch
// =====================================================================
extern "C" void kernel_launch(void* const* d_in, const int* in_sizes, int n_in,
                              void* d_out, int out_size)
{
    const float* x  = (const float*)d_in[0];
    const float* wq = (const float*)d_in[1];
    const float* wk = (const float*)d_in[2];
    const float* wv = (const float*)d_in[3];
    const float* wo = (const float*)d_in[4];
    float* out = (float*)d_out;

    float *gq, *gk, *ct, *st;
    __nv_bfloat16 *ahi, *alo, *wthi, *wtlo, *qh, *ql, *kh, *kl, *vh, *vl;
    cudaGetSymbolAddress((void**)&gq, g_q);
    cudaGetSymbolAddress((void**)&gk, g_k);
    cudaGetSymbolAddress((void**)&ct, g_cos);
    cudaGetSymbolAddress((void**)&st, g_sin);
    cudaGetSymbolAddress((void**)&ahi, g_ahi);
    cudaGetSymbolAddress((void**)&alo, g_alo);
    cudaGetSymbolAddress((void**)&wthi, g_wthi);
    cudaGetSymbolAddress((void**)&wtlo, g_wtlo);
    cudaGetSymbolAddress((void**)&qh, g_qh);
    cudaGetSymbolAddress((void**)&ql, g_ql);
    cudaGetSymbolAddress((void**)&kh, g_kh);
    cudaGetSymbolAddress((void**)&kl, g_kl);
    cudaGetSymbolAddress((void**)&vh, g_vh);
    cudaGetSymbolAddress((void**)&vl, g_vl);

    cudaFuncSetAttribute(mma_gemm_kernel,
                         cudaFuncAttributeMaxDynamicSharedMemorySize, GEMM_SMEM);
    cudaFuncSetAttribute(flash_mma_kernel,
                         cudaFuncAttributeMaxDynamicSharedMemorySize, FL_SMEM);

    const int n4 = (int)(ELEMS / 4);
    const dim3 sgrid((n4 + 255) / 256);
    const dim3 wgrid(EMB / 32, EMB / 32);
    const size_t WSZ = (size_t)EMB * EMB;

    // prep: split x, weights, rope tables
    split_kernel<<<sgrid, 256>>>(x, ahi, alo, n4);
    wsplit_kernel<<<wgrid, 256>>>(wq, wthi, wtlo);
    wsplit_kernel<<<wgrid, 256>>>(wk, wthi + WSZ, wtlo + WSZ);
    wsplit_kernel<<<wgrid, 256>>>(wv, wthi + 2 * WSZ, wtlo + 2 * WSZ);
    wsplit_kernel<<<wgrid, 256>>>(wo, wthi + 3 * WSZ, wtlo + 3 * WSZ);
    rope_table_kernel<<<(SEQ * 64 + 255) / 256, 256>>>(ct, st);

    // fused QKV GEMM: q,k fp32; v directly bf16 hi/lo
    dim3 qkvgrid(3 * EMB / BN, MROWS / BM);   // (24, 64)
    mma_gemm_kernel<<<qkvgrid, 256, GEMM_SMEM>>>(
        ahi, alo, wthi, wtlo, EMB, 1, gq, gk, vh, vl);

    // RoPE + RMSNorm + split (scale folded into Q)
    dim3 rgrid(NHEAD, SEQ, BATCH);
    ropeprep_kernel<<<rgrid, 64>>>(gq, ct, st, qh, ql, 0.08838834764831845f);
    ropeprep_kernel<<<rgrid, 64>>>(gk, ct, st, kh, kl, 1.0f);

    // flash attention -> writes ahi/alo (bf16 hi/lo) directly
    dim3 fgrid(SEQ / 128, NHEAD, BATCH);
    flash_mma_kernel<<<fgrid, 256, FL_SMEM>>>(qh, ql, kh, kl, vh, vl, ahi, alo);

    // out = y @ wo
    dim3 ogrid(EMB / BN, MROWS / BM);
    mma_gemm_kernel<<<ogrid, 256, GEMM_SMEM>>>(
        ahi, alo, wthi + 3 * WSZ, wtlo + 3 * WSZ, EMB, 0, out, nullptr, nullptr, nullptr);
}